// round 13
// baseline (speedup 1.0000x reference)
#include <cuda_runtime.h>
#include <cuda_bf16.h>
#include <math.h>
#include <stdint.h>

#define B_ 128
#define T_ 512
#define D_ 128
#define H_ 512
#define G_ 2048          // 4*H
#define EPS_ 1e-3f
#define NBLK_ 128
#define MR_ (B_ * T_)    // 65536

// ---------------- scratch (static device allocations) -----------------------
__device__ __align__(16) float g_xz[(size_t)B_ * T_ * G_];
__device__ __align__(16) __nv_bfloat16 g_seqA[(size_t)B_ * T_ * H_];
__device__ __align__(16) __nv_bfloat16 g_seqB[(size_t)B_ * T_ * H_];
__device__ __align__(16) float g_seq32[(size_t)B_ * T_ * H_];
__device__ __align__(16) __nv_bfloat16 g_hbuf[2 * B_ * H_];
__device__ __align__(16) float g_spart[4 * MR_];
__device__ __align__(16) float g_s[MR_];
__device__ __align__(16) float g_pool[B_ * H_];
__device__ volatile int g_bar_count;
__device__ volatile int g_bar_sense;
__device__ int g_flags[NBLK_ * 32];  // one 128B line per block

// ---------------- helpers ----------------------------------------------------
__device__ __forceinline__ uint32_t packbf(float lo, float hi) {
  __nv_bfloat162 v = __floats2bfloat162_rn(lo, hi);
  return *(uint32_t*)&v;
}
__device__ __forceinline__ void mma_bf16(float* d, const uint32_t* a,
                                         const uint32_t* b) {
  asm("mma.sync.aligned.m16n8k16.row.col.f32.bf16.bf16.f32 "
      "{%0,%1,%2,%3}, {%4,%5,%6,%7}, {%8,%9}, {%0,%1,%2,%3};"
      : "+f"(d[0]), "+f"(d[1]), "+f"(d[2]), "+f"(d[3])
      : "r"(a[0]), "r"(a[1]), "r"(a[2]), "r"(a[3]), "r"(b[0]), "r"(b[1]));
}
__device__ __forceinline__ void ldsm4(uint32_t& r0, uint32_t& r1, uint32_t& r2,
                                      uint32_t& r3, uint32_t addr) {
  asm volatile(
      "ldmatrix.sync.aligned.m8n8.x4.shared.b16 {%0,%1,%2,%3}, [%4];"
      : "=r"(r0), "=r"(r1), "=r"(r2), "=r"(r3) : "r"(addr));
}
__device__ __forceinline__ float tanha(float x) {
  float y;
  asm("tanh.approx.f32 %0, %1;" : "=f"(y) : "f"(x));
  return y;
}
__device__ __forceinline__ float siga(float x) {
  return fmaf(tanha(0.5f * x), 0.5f, 0.5f);
}

__device__ __forceinline__ void grid_bar_atomic(int& ls) {
  __syncthreads();
  if (threadIdx.x == 0) {
    __threadfence();
    const int s = ls ^ 1;
    ls = s;
    if (atomicAdd((int*)&g_bar_count, 1) == NBLK_ - 1) {
      g_bar_count = 0;
      __threadfence();
      g_bar_sense = s;
    } else {
      while (g_bar_sense != s) { }
    }
    __threadfence();
  }
  __syncthreads();
}

__device__ __forceinline__ void bar_release(int phase) {
  __syncthreads();
  if (threadIdx.x == 0) {
    asm volatile("st.release.gpu.global.b32 [%0], %1;"
                 :: "l"(&g_flags[blockIdx.x * 32]), "r"(phase) : "memory");
  }
}

// ---------------- bf16 tensor GEMM: C = A[M,K]@W[K,N] + bias ----------------
template <bool ABF16, bool ATTN>
__global__ __launch_bounds__(256) void gemm_bf16k(
    const void* __restrict__ Av, const float* __restrict__ W,
    const float* __restrict__ bias, float* __restrict__ C,
    float* __restrict__ spart, int K, int N) {
  __shared__ uint32_t As[128][36];
  __shared__ uint32_t Bs[128][36];
  __shared__ float srow[128][2];
  const int tid = threadIdx.x;
  const int warp = tid >> 5, lane = tid & 31;
  const int wm = warp >> 1, wn = warp & 1;
  const int m0 = wm * 32, n0 = wn * 64;
  const int r = lane >> 2, c4 = lane & 3;
  const int row0 = blockIdx.y * 128, col0 = blockIdx.x * 128;
  const int quad = lane >> 3, l7 = lane & 7;
  const int lrow = l7 + ((quad & 1) << 3);
  const int lkof = (quad >> 1) << 2;

  float acc[2][8][4];
#pragma unroll
  for (int i = 0; i < 2; i++)
#pragma unroll
    for (int j = 0; j < 8; j++)
#pragma unroll
      for (int k = 0; k < 4; k++) acc[i][j][k] = 0.f;

  uint32_t aB[2], bB[4];
#pragma unroll
  for (int mf = 0; mf < 2; mf++)
    aB[mf] = (uint32_t)__cvta_generic_to_shared(&As[m0 + mf * 16 + lrow][lkof]);
#pragma unroll
  for (int p = 0; p < 4; p++)
    bB[p] = (uint32_t)__cvta_generic_to_shared(&Bs[n0 + p * 16 + lrow][lkof]);

  uint4 va[4];
  float4 va32[8];
  float4 vb[8];
  if (ABF16) {
    const __nv_bfloat16* A = (const __nv_bfloat16*)Av;
#pragma unroll
    for (int i = 0; i < 4; i++) {
      const int f = tid + i * 256;
      va[i] = *(const uint4*)&A[(size_t)(row0 + (f >> 3)) * K + (f & 7) * 8];
    }
  } else {
    const float* A = (const float*)Av;
#pragma unroll
    for (int i = 0; i < 8; i++) {
      const int f = tid + i * 256;
      va32[i] = *(const float4*)&A[(size_t)(row0 + (f >> 4)) * K + (f & 15) * 4];
    }
  }
#pragma unroll
  for (int i = 0; i < 4; i++) {
    const int g = tid + i * 256;
    const int n4 = g & 31, k2 = g >> 5;
    vb[2 * i] = *(const float4*)&W[(size_t)(2 * k2) * N + col0 + n4 * 4];
    vb[2 * i + 1] = *(const float4*)&W[(size_t)(2 * k2 + 1) * N + col0 + n4 * 4];
  }

  for (int kt = 0; kt < K; kt += 64) {
    __syncthreads();
    if (ABF16) {
#pragma unroll
      for (int i = 0; i < 4; i++) {
        const int f = tid + i * 256;
        *(uint4*)&As[f >> 3][(f & 7) * 4] = va[i];
      }
    } else {
#pragma unroll
      for (int i = 0; i < 8; i++) {
        const int f = tid + i * 256;
        const int row = f >> 4, k4 = f & 15;
        As[row][k4 * 2 + 0] = packbf(va32[i].x, va32[i].y);
        As[row][k4 * 2 + 1] = packbf(va32[i].z, va32[i].w);
      }
    }
#pragma unroll
    for (int i = 0; i < 4; i++) {
      const int g = tid + i * 256;
      const int n4 = g & 31, k2 = g >> 5;
      const float4 lo = vb[2 * i], hi = vb[2 * i + 1];
      Bs[n4 * 4 + 0][k2] = packbf(lo.x, hi.x);
      Bs[n4 * 4 + 1][k2] = packbf(lo.y, hi.y);
      Bs[n4 * 4 + 2][k2] = packbf(lo.z, hi.z);
      Bs[n4 * 4 + 3][k2] = packbf(lo.w, hi.w);
    }
    __syncthreads();
    if (kt + 64 < K) {
      if (ABF16) {
        const __nv_bfloat16* A = (const __nv_bfloat16*)Av;
#pragma unroll
        for (int i = 0; i < 4; i++) {
          const int f = tid + i * 256;
          va[i] = *(const uint4*)&A[(size_t)(row0 + (f >> 3)) * K + kt + 64 +
                                    (f & 7) * 8];
        }
      } else {
        const float* A = (const float*)Av;
#pragma unroll
        for (int i = 0; i < 8; i++) {
          const int f = tid + i * 256;
          va32[i] = *(const float4*)&A[(size_t)(row0 + (f >> 4)) * K + kt + 64 +
                                       (f & 15) * 4];
        }
      }
#pragma unroll
      for (int i = 0; i < 4; i++) {
        const int g = tid + i * 256;
        const int n4 = g & 31, k2 = g >> 5;
        vb[2 * i] =
            *(const float4*)&W[(size_t)(kt + 64 + 2 * k2) * N + col0 + n4 * 4];
        vb[2 * i + 1] = *(const float4*)&W[(size_t)(kt + 64 + 2 * k2 + 1) * N +
                                           col0 + n4 * 4];
      }
    }
#pragma unroll
    for (int ck = 0; ck < 4; ck++) {
      const uint32_t koff = ck * 32;
      uint32_t af[2][4], bf[8][2];
#pragma unroll
      for (int mf = 0; mf < 2; mf++)
        ldsm4(af[mf][0], af[mf][1], af[mf][2], af[mf][3], aB[mf] + koff);
#pragma unroll
      for (int p = 0; p < 4; p++)
        ldsm4(bf[2 * p][0], bf[2 * p + 1][0], bf[2 * p][1], bf[2 * p + 1][1],
              bB[p] + koff);
#pragma unroll
      for (int mf = 0; mf < 2; mf++)
#pragma unroll
        for (int nf = 0; nf < 8; nf++) mma_bf16(acc[mf][nf], af[mf], bf[nf]);
    }
  }

  if (!ATTN) {
#pragma unroll
    for (int mf = 0; mf < 2; mf++) {
#pragma unroll
      for (int nf = 0; nf < 8; nf++) {
        const int cc = col0 + n0 + nf * 8 + c4 * 2;
        const float b0 = bias[cc], b1 = bias[cc + 1];
        const int rr = row0 + m0 + mf * 16 + r;
        *(float2*)&C[(size_t)rr * N + cc] =
            make_float2(acc[mf][nf][0] + b0, acc[mf][nf][1] + b1);
        *(float2*)&C[(size_t)(rr + 8) * N + cc] =
            make_float2(acc[mf][nf][2] + b0, acc[mf][nf][3] + b1);
      }
    }
  } else {
    float s0[2] = {0.f, 0.f}, s1[2] = {0.f, 0.f};
#pragma unroll
    for (int mf = 0; mf < 2; mf++) {
#pragma unroll
      for (int nf = 0; nf < 8; nf++) {
        const int cc = col0 + n0 + nf * 8 + c4 * 2;
        const float b0 = bias[cc], b1 = bias[cc + 1];
        s0[mf] += tanhf(acc[mf][nf][0] + b0) + tanhf(acc[mf][nf][1] + b1);
        s1[mf] += tanhf(acc[mf][nf][2] + b0) + tanhf(acc[mf][nf][3] + b1);
      }
#pragma unroll
      for (int o = 1; o < 4; o <<= 1) {
        s0[mf] += __shfl_xor_sync(0xFFFFFFFFu, s0[mf], o);
        s1[mf] += __shfl_xor_sync(0xFFFFFFFFu, s1[mf], o);
      }
    }
    if (c4 == 0) {
#pragma unroll
      for (int mf = 0; mf < 2; mf++) {
        srow[m0 + mf * 16 + r][wn] = s0[mf];
        srow[m0 + mf * 16 + 8 + r][wn] = s1[mf];
      }
    }
    __syncthreads();
    if (tid < 128)
      spart[(size_t)blockIdx.x * MR_ + row0 + tid] = srow[tid][0] + srow[tid][1];
  }
}

// ---------------- persistent LSTM scan --------------------------------------
// Grid 128 = 8 groups (mb) x 16 blocks (jb). Block: 16 batches x 32 h-cols.
// ARRIVAL-ORDERED CONSUMPTION: mma decomposed by peer k-slice; A-fragments
// loaded per-peer straight from gmem (no smem staging, no pre-mma block sync).
// 4 fixed-order accumulator groups keep FP accumulation deterministic while
// groups are processed in arrival order.
#define SCPAD 260
#define ZPAD 33
#define SMEM_SCAN (128 * SCPAD * 4 + 4 * 16 * ZPAD * 4)

// one peer's k-slice chunk pair into ACC (fixed order inside groups)
#define PROC_PEER(P, ACC) do {                                              \
    const int k2o = (P) * 16;                                               \
    uint32_t af[4], b00, b10, b01, b11;                                     \
    af[0] = __ldcg(hrow1 + k2o + c4);                                       \
    af[1] = __ldcg(hrow2 + k2o + c4);                                       \
    af[2] = __ldcg(hrow1 + k2o + c4 + 4);                                   \
    af[3] = __ldcg(hrow2 + k2o + c4 + 4);                                   \
    ldsm4(b00, b10, b01, b11, bBase + (uint32_t)k2o * 4);                   \
    {                                                                       \
      uint32_t bf0[2] = {b00, b01}, bf1[2] = {b10, b11};                    \
      mma_bf16(ACC[0], af, bf0);                                            \
      mma_bf16(ACC[1], af, bf1);                                            \
    }                                                                       \
    af[0] = __ldcg(hrow1 + k2o + 8 + c4);                                   \
    af[1] = __ldcg(hrow2 + k2o + 8 + c4);                                   \
    af[2] = __ldcg(hrow1 + k2o + 8 + c4 + 4);                               \
    af[3] = __ldcg(hrow2 + k2o + 8 + c4 + 4);                               \
    ldsm4(b00, b10, b01, b11, bBase + (uint32_t)k2o * 4 + 32);              \
    {                                                                       \
      uint32_t bf0[2] = {b00, b01}, bf1[2] = {b10, b11};                    \
      mma_bf16(ACC[0], af, bf0);                                            \
      mma_bf16(ACC[1], af, bf1);                                            \
    }                                                                       \
  } while (0)

__global__ __launch_bounds__(256) void lstm_scan(
    const float* __restrict__ xz, const float* __restrict__ U,
    __nv_bfloat16* __restrict__ seqbf, float* __restrict__ seq32,
    __nv_bfloat16* __restrict__ hbuf,
    const float* __restrict__ bng, const float* __restrict__ bnb,
    const float* __restrict__ bnm, const float* __restrict__ bnv,
    int apply_bn, int w32) {
  extern __shared__ uint32_t dsm[];
  uint32_t(*Us)[SCPAD] = (uint32_t(*)[SCPAD])dsm;       // [128][260]
  float* zbuf = (float*)(dsm + 128 * SCPAD);            // [4][16][33]

  const int bid = blockIdx.x, tid = threadIdx.x;
  const int mb = bid >> 4, jb = bid & 15;
  const int j0 = jb * 32, b0g = mb * 16;
  const int gbase = mb * 16;
  const int warp = tid >> 5, lane = tid & 31;
  const int q = warp >> 1, half = warp & 1;
  const int r = lane >> 2, c4 = lane & 3;
  const int quad = lane >> 3, l7 = lane & 7;
  const int lrow = l7 + ((quad & 1) << 3);
  const int lkof = (quad >> 1) << 2;

  // stage U tile once: Us[n][k2], n = q*32 + local col, bf16x2 in k
#pragma unroll
  for (int i = 0; i < 32; i++) {
    const int g = tid + i * 256;
    const int n4 = g & 31, k2 = g >> 5;
    const int qq = n4 >> 3, cg = n4 & 7;
    const int gcol = qq * 512 + j0 + cg * 4;
    const float4 lo = *(const float4*)&U[(size_t)(2 * k2) * G_ + gcol];
    const float4 hi = *(const float4*)&U[(size_t)(2 * k2 + 1) * G_ + gcol];
    Us[n4 * 4 + 0][k2] = packbf(lo.x, hi.x);
    Us[n4 * 4 + 1][k2] = packbf(lo.y, hi.y);
    Us[n4 * 4 + 2][k2] = packbf(lo.z, hi.z);
    Us[n4 * 4 + 3][k2] = packbf(lo.w, hi.w);
  }

  const uint32_t bBase = (uint32_t)__cvta_generic_to_shared(
      &Us[q * 32 + half * 16 + lrow][lkof]);

  // per-thread gate-cell ownership: 16 batches x 32 cols, 2 cols/thread
  const int bl = tid >> 4, jj = (tid & 15) * 2;
  const int bg = b0g + bl, jgl = j0 + jj;
  float c1 = 0.f, c2 = 0.f;
  float scl1 = 1.f, sft1 = 0.f, scl2 = 1.f, sft2 = 0.f;
  if (apply_bn) {
    scl1 = rsqrtf(bnv[jgl] + EPS_) * bng[jgl];
    sft1 = bnb[jgl] - bnm[jgl] * scl1;
    scl2 = rsqrtf(bnv[jgl + 1] + EPS_) * bng[jgl + 1];
    sft2 = bnb[jgl + 1] - bnm[jgl + 1] * scl2;
  }
  __nv_bfloat16* hw_base = hbuf + (size_t)bg * H_ + jgl;

  const float* xzb1 = xz + ((size_t)(b0g + r) * T_) * G_ + q * 512 + j0 + half * 16;
  const float* xzb2 = xz + ((size_t)(b0g + 8 + r) * T_) * G_ + q * 512 + j0 + half * 16;
  float2 xp[4];
#pragma unroll
  for (int nf = 0; nf < 2; nf++) {
    const int cA = nf * 8 + c4 * 2;
    xp[nf * 2 + 0] = __ldg((const float2*)(xzb1 + cA));
    xp[nf * 2 + 1] = __ldg((const float2*)(xzb2 + cA));
  }

  int ls = 0;
  if (tid == 0) {
    ls = g_bar_sense;
    g_flags[bid * 32] = 0;
  }
  grid_bar_atomic(ls);

  for (int t = 0; t < T_; t++) {
    float acc0[2][4], acc1[2][4], acc2[2][4], acc3[2][4];
#pragma unroll
    for (int i = 0; i < 2; i++)
#pragma unroll
      for (int j = 0; j < 4; j++) {
        acc0[i][j] = 0.f; acc1[i][j] = 0.f;
        acc2[i][j] = 0.f; acc3[i][j] = 0.f;
      }

    if (t > 0) {
      const uint32_t* hsrc32 =
          (const uint32_t*)(hbuf + (size_t)(t & 1) * B_ * H_);
      const uint32_t* hrow1 = hsrc32 + (size_t)(b0g + r) * 256;
      const uint32_t* hrow2 = hsrc32 + (size_t)(b0g + 8 + r) * 256;

      unsigned remg = 0xFu;
      while (remg) {
        int okp = 0;
        if (lane < 16) {
          int v;
          asm volatile("ld.acquire.gpu.global.b32 %0, [%1];"
                       : "=r"(v) : "l"(&g_flags[(gbase + lane) * 32]));
          okp = (v >= t);
        }
        unsigned rdy = __ballot_sync(0xFFFFFFFFu, okp);
        unsigned gm = 0;
        if ((rdy & 0x000Fu) == 0x000Fu) gm |= 1u;
        if ((rdy & 0x00F0u) == 0x00F0u) gm |= 2u;
        if ((rdy & 0x0F00u) == 0x0F00u) gm |= 4u;
        if ((rdy & 0xF000u) == 0xF000u) gm |= 8u;
        gm &= remg;
        __syncwarp();  // fence: observed peers' h stores ordered for all lanes
        if (gm & 1u) {
          PROC_PEER(0, acc0); PROC_PEER(1, acc0);
          PROC_PEER(2, acc0); PROC_PEER(3, acc0);
          remg &= ~1u;
        }
        if (gm & 2u) {
          PROC_PEER(4, acc1); PROC_PEER(5, acc1);
          PROC_PEER(6, acc1); PROC_PEER(7, acc1);
          remg &= ~2u;
        }
        if (gm & 4u) {
          PROC_PEER(8, acc2); PROC_PEER(9, acc2);
          PROC_PEER(10, acc2); PROC_PEER(11, acc2);
          remg &= ~4u;
        }
        if (gm & 8u) {
          PROC_PEER(12, acc3); PROC_PEER(13, acc3);
          PROC_PEER(14, acc3); PROC_PEER(15, acc3);
          remg &= ~8u;
        }
      }
    }

    // z = ((acc0+acc1)+(acc2+acc3)) + xz -> zbuf[q][batch][col32]
#pragma unroll
    for (int nf = 0; nf < 2; nf++) {
      const int col = half * 16 + nf * 8 + c4 * 2;
      float* zb = zbuf + (size_t)q * 16 * ZPAD;
#pragma unroll
      for (int k = 0; k < 4; k++) {
        const float zv = (acc0[nf][k] + acc1[nf][k]) +
                         (acc2[nf][k] + acc3[nf][k]);
        const float xv = (k == 0) ? xp[nf * 2 + 0].x
                        : (k == 1) ? xp[nf * 2 + 0].y
                        : (k == 2) ? xp[nf * 2 + 1].x
                                   : xp[nf * 2 + 1].y;
        const int rw = (k < 2) ? r : (r + 8);
        zb[rw * ZPAD + col + (k & 1)] = zv + xv;
      }
    }
    __syncthreads();

    const float zi1 = zbuf[(0 * 16 + bl) * ZPAD + jj];
    const float zi2 = zbuf[(0 * 16 + bl) * ZPAD + jj + 1];
    const float zf1 = zbuf[(1 * 16 + bl) * ZPAD + jj];
    const float zf2 = zbuf[(1 * 16 + bl) * ZPAD + jj + 1];
    const float zg1 = zbuf[(2 * 16 + bl) * ZPAD + jj];
    const float zg2 = zbuf[(2 * 16 + bl) * ZPAD + jj + 1];
    const float zo1 = zbuf[(3 * 16 + bl) * ZPAD + jj];
    const float zo2 = zbuf[(3 * 16 + bl) * ZPAD + jj + 1];

    if (t + 1 < T_) {
#pragma unroll
      for (int nf = 0; nf < 2; nf++) {
        const int cA = nf * 8 + c4 * 2;
        xp[nf * 2 + 0] = __ldg((const float2*)(xzb1 + (size_t)(t + 1) * G_ + cA));
        xp[nf * 2 + 1] = __ldg((const float2*)(xzb2 + (size_t)(t + 1) * G_ + cA));
      }
    }

    const float i1 = siga(zi1), f1 = siga(zf1), g1 = tanha(zg1), o1 = siga(zo1);
    c1 = f1 * c1 + i1 * g1;
    const float h1 = o1 * tanha(c1);
    const float i2 = siga(zi2), f2 = siga(zf2), g2 = tanha(zg2), o2 = siga(zo2);
    c2 = f2 * c2 + i2 * g2;
    const float h2 = o2 * tanha(c2);

    *(uint32_t*)(hw_base + (size_t)((t + 1) & 1) * B_ * H_) = packbf(h1, h2);
    bar_release(t + 1);

    const float s1v = apply_bn ? (h1 * scl1 + sft1) : h1;
    const float s2v = apply_bn ? (h2 * scl2 + sft2) : h2;
    *(uint32_t*)&seqbf[((size_t)bg * T_ + t) * H_ + jgl] = packbf(s1v, s2v);
    if (w32)
      *(float2*)&seq32[((size_t)bg * T_ + t) * H_ + jgl] = make_float2(s1v, s2v);
  }
}

// ---------------- attention tail / head -------------------------------------
__global__ void rowsum_final(const float* __restrict__ sp,
                             float* __restrict__ s) {
  const int i = blockIdx.x * blockDim.x + threadIdx.x;
  s[i] = sp[i] + sp[MR_ + i] + sp[2 * MR_ + i] + sp[3 * MR_ + i];
}

__global__ __launch_bounds__(512) void softmax_kernel(float* __restrict__ s) {
  __shared__ float red[T_];
  const int b = blockIdx.x, t = threadIdx.x;
  const float v = s[b * T_ + t];
  red[t] = v;
  __syncthreads();
  for (int o = 256; o; o >>= 1) {
    if (t < o) red[t] = fmaxf(red[t], red[t + o]);
    __syncthreads();
  }
  const float m = red[0];
  __syncthreads();
  const float ev = expf(v - m);
  red[t] = ev;
  __syncthreads();
  for (int o = 256; o; o >>= 1) {
    if (t < o) red[t] += red[t + o];
    __syncthreads();
  }
  s[b * T_ + t] = ev / red[0];
}

__global__ __launch_bounds__(512) void pool_kernel(const float* __restrict__ seq,
                                                   const float* __restrict__ a,
                                                   float* __restrict__ pool) {
  const int b = blockIdx.x, d = threadIdx.x;
  const float* p = seq + (size_t)b * T_ * H_ + d;
  const float* ap = a + b * T_;
  float acc = 0.f;
  for (int t = 0; t < T_; t++) acc += ap[t] * p[(size_t)t * H_];
  pool[b * H_ + d] = acc * (1.0f / T_);
}

__global__ __launch_bounds__(128) void head_kernel(
    const float* __restrict__ pool,
    const float* __restrict__ Wd1, const float* __restrict__ bd1,
    const float* __restrict__ bng, const float* __restrict__ bnb,
    const float* __restrict__ bnm, const float* __restrict__ bnv,
    const float* __restrict__ Wd2, const float* __restrict__ bd2,
    const float* __restrict__ Wd3, const float* __restrict__ bd3,
    float* __restrict__ out) {
  __shared__ float sp[H_];
  __shared__ float d1[128];
  __shared__ float d2[64];
  const int b = blockIdx.x, t = threadIdx.x;
  for (int i = t; i < H_; i += 128) sp[i] = pool[b * H_ + i];
  __syncthreads();
  {
    float acc = bd1[t];
    for (int k = 0; k < H_; k++) acc += sp[k] * Wd1[k * 128 + t];
    acc = fmaxf(acc, 0.f);
    acc = (acc - bnm[t]) * rsqrtf(bnv[t] + EPS_) * bng[t] + bnb[t];
    d1[t] = acc;
  }
  __syncthreads();
  if (t < 64) {
    float acc = bd2[t];
    for (int k = 0; k < 128; k++) acc += d1[k] * Wd2[k * 64 + t];
    d2[t] = fmaxf(acc, 0.f);
  }
  __syncthreads();
  if (t < 5) {
    float acc = bd3[t];
    for (int k = 0; k < 64; k++) acc += d2[k] * Wd3[k * 5 + t];
    out[b * 5 + t] = acc;
  }
}

// ---------------- launch ----------------------------------------------------
extern "C" void kernel_launch(void* const* d_in, const int* in_sizes, int n_in,
                              void* d_out, int out_size) {
  (void)out_size;
  static const int sig_map[30] = {0, 1, 2, 3, 8, 9, 10, 15, 16, 17,
                                  4, 5, 6, 7, 11, 12, 13, 14, 22, 23,
                                  24, 25, 18, 19, 20, 21, 26, 27, 28, 29};
  const int setup_order = (n_in >= 5 && in_sizes[4] == 1048576) ? 1 : 0;
  const float* in[30];
  for (int i = 0; i < 30; i++)
    in[i] = (const float*)d_in[setup_order ? i : sig_map[i]];

  const float* x = in[0];
  const float* Wl[3] = {in[1], in[4], in[7]};
  const float* Ul[3] = {in[2], in[5], in[8]};
  const float* bl[3] = {in[3], in[6], in[9]};
  const float* bng[3] = {in[10], in[14], in[18]};
  const float* bnb[3] = {in[11], in[15], in[19]};
  const float* bnm[3] = {in[12], in[16], in[20]};
  const float* bnv[3] = {in[13], in[17], in[21]};
  const float* Wa = in[22];  const float* ba = in[23];
  const float* Wd1 = in[24]; const float* bd1 = in[25];
  const float* Wd2 = in[26]; const float* bd2 = in[27];
  const float* Wd3 = in[28]; const float* bd3 = in[29];

  float *xz, *seq32, *spart, *s, *pool;
  __nv_bfloat16 *seqA, *seqB, *hbuf;
  cudaGetSymbolAddress((void**)&xz, g_xz);
  cudaGetSymbolAddress((void**)&seqA, g_seqA);
  cudaGetSymbolAddress((void**)&seqB, g_seqB);
  cudaGetSymbolAddress((void**)&seq32, g_seq32);
  cudaGetSymbolAddress((void**)&hbuf, g_hbuf);
  cudaGetSymbolAddress((void**)&spart, g_spart);
  cudaGetSymbolAddress((void**)&s, g_s);
  cudaGetSymbolAddress((void**)&pool, g_pool);

  cudaFuncSetAttribute(lstm_scan, cudaFuncAttributeMaxDynamicSharedMemorySize,
                       SMEM_SCAN);

  gemm_bf16k<false, false><<<dim3(G_ / 128, MR_ / 128), 256>>>(
      x, Wl[0], bl[0], xz, nullptr, D_, G_);
  lstm_scan<<<NBLK_, 256, SMEM_SCAN>>>(xz, Ul[0], seqA, seq32, hbuf,
                                       bng[0], bnb[0], bnm[0], bnv[0], 1, 0);
  gemm_bf16k<true, false><<<dim3(G_ / 128, MR_ / 128), 256>>>(
      seqA, Wl[1], bl[1], xz, nullptr, H_, G_);
  lstm_scan<<<NBLK_, 256, SMEM_SCAN>>>(xz, Ul[1], seqB, seq32, hbuf,
                                       bng[1], bnb[1], bnm[1], bnv[1], 1, 0);
  gemm_bf16k<true, false><<<dim3(G_ / 128, MR_ / 128), 256>>>(
      seqB, Wl[2], bl[2], xz, nullptr, H_, G_);
  lstm_scan<<<NBLK_, 256, SMEM_SCAN>>>(xz, Ul[2], seqA, seq32, hbuf,
                                       bng[2], bnb[2], bnm[2], bnv[2], 0, 1);

  gemm_bf16k<true, true><<<dim3(H_ / 128, MR_ / 128), 256>>>(
      seqA, Wa, ba, nullptr, spart, H_, H_);
  rowsum_final<<<MR_ / 256, 256>>>(spart, s);
  softmax_kernel<<<B_, T_>>>(s);
  pool_kernel<<<B_, H_>>>(seq32, s, pool);
  head_kernel<<<B_, 128>>>(pool, Wd1, bd1, bng[2], bnb[2], bnm[2], bnv[2],
                           Wd2, bd2, Wd3, bd3, (float*)d_out);
}

// round 14
// speedup vs baseline: 2.4267x; 2.4267x over previous
#include <cuda_runtime.h>
#include <cuda_bf16.h>
#include <math.h>
#include <stdint.h>

#define B_ 128
#define T_ 512
#define D_ 128
#define H_ 512
#define G_ 2048          // 4*H
#define EPS_ 1e-3f
#define NBLK_ 128
#define MR_ (B_ * T_)    // 65536

// ---------------- scratch (static device allocations) -----------------------
__device__ __align__(16) __nv_bfloat16 g_xz[(size_t)B_ * T_ * G_];  // bf16 xz
__device__ __align__(16) __nv_bfloat16 g_seqA[(size_t)B_ * T_ * H_];
__device__ __align__(16) __nv_bfloat16 g_seqB[(size_t)B_ * T_ * H_];
__device__ __align__(16) float g_seq32[(size_t)B_ * T_ * H_];
__device__ __align__(16) __nv_bfloat16 g_hbuf[2 * B_ * H_];
__device__ __align__(16) float g_spart[4 * MR_];
__device__ __align__(16) float g_s[MR_];
__device__ __align__(16) float g_pool[B_ * H_];
__device__ volatile int g_bar_count;
__device__ volatile int g_bar_sense;
__device__ int g_flags[NBLK_ * 32];  // one 128B line per block

// ---------------- helpers ----------------------------------------------------
__device__ __forceinline__ uint32_t packbf(float lo, float hi) {
  __nv_bfloat162 v = __floats2bfloat162_rn(lo, hi);
  return *(uint32_t*)&v;
}
__device__ __forceinline__ float2 unpackbf(uint32_t u) {
  __nv_bfloat162 v = *(__nv_bfloat162*)&u;
  return __bfloat1622float2(v);
}
__device__ __forceinline__ void mma_bf16(float* d, const uint32_t* a,
                                         const uint32_t* b) {
  asm("mma.sync.aligned.m16n8k16.row.col.f32.bf16.bf16.f32 "
      "{%0,%1,%2,%3}, {%4,%5,%6,%7}, {%8,%9}, {%0,%1,%2,%3};"
      : "+f"(d[0]), "+f"(d[1]), "+f"(d[2]), "+f"(d[3])
      : "r"(a[0]), "r"(a[1]), "r"(a[2]), "r"(a[3]), "r"(b[0]), "r"(b[1]));
}
__device__ __forceinline__ void ldsm4(uint32_t& r0, uint32_t& r1, uint32_t& r2,
                                      uint32_t& r3, uint32_t addr) {
  asm volatile(
      "ldmatrix.sync.aligned.m8n8.x4.shared.b16 {%0,%1,%2,%3}, [%4];"
      : "=r"(r0), "=r"(r1), "=r"(r2), "=r"(r3) : "r"(addr));
}
__device__ __forceinline__ float tanha(float x) {
  float y;
  asm("tanh.approx.f32 %0, %1;" : "=f"(y) : "f"(x));
  return y;
}
__device__ __forceinline__ float siga(float x) {
  return fmaf(tanha(0.5f * x), 0.5f, 0.5f);
}

__device__ __forceinline__ void grid_bar_atomic(int& ls) {
  __syncthreads();
  if (threadIdx.x == 0) {
    __threadfence();
    const int s = ls ^ 1;
    ls = s;
    if (atomicAdd((int*)&g_bar_count, 1) == NBLK_ - 1) {
      g_bar_count = 0;
      __threadfence();
      g_bar_sense = s;
    } else {
      while (g_bar_sense != s) { }
    }
    __threadfence();
  }
  __syncthreads();
}

__device__ __forceinline__ void bar_release(int phase) {
  __syncthreads();
  if (threadIdx.x == 0) {
    asm volatile("st.release.gpu.global.b32 [%0], %1;"
                 :: "l"(&g_flags[blockIdx.x * 32]), "r"(phase) : "memory");
  }
}

// ---------------- bf16 tensor GEMM: Cbf16 = A[M,K]@W[K,N] + bias ------------
template <bool ABF16, bool ATTN>
__global__ __launch_bounds__(256) void gemm_bf16k(
    const void* __restrict__ Av, const float* __restrict__ W,
    const float* __restrict__ bias, __nv_bfloat16* __restrict__ C,
    float* __restrict__ spart, int K, int N) {
  __shared__ uint32_t As[128][36];
  __shared__ uint32_t Bs[128][36];
  __shared__ float srow[128][2];
  const int tid = threadIdx.x;
  const int warp = tid >> 5, lane = tid & 31;
  const int wm = warp >> 1, wn = warp & 1;
  const int m0 = wm * 32, n0 = wn * 64;
  const int r = lane >> 2, c4 = lane & 3;
  const int row0 = blockIdx.y * 128, col0 = blockIdx.x * 128;
  const int quad = lane >> 3, l7 = lane & 7;
  const int lrow = l7 + ((quad & 1) << 3);
  const int lkof = (quad >> 1) << 2;

  float acc[2][8][4];
#pragma unroll
  for (int i = 0; i < 2; i++)
#pragma unroll
    for (int j = 0; j < 8; j++)
#pragma unroll
      for (int k = 0; k < 4; k++) acc[i][j][k] = 0.f;

  uint32_t aB[2], bB[4];
#pragma unroll
  for (int mf = 0; mf < 2; mf++)
    aB[mf] = (uint32_t)__cvta_generic_to_shared(&As[m0 + mf * 16 + lrow][lkof]);
#pragma unroll
  for (int p = 0; p < 4; p++)
    bB[p] = (uint32_t)__cvta_generic_to_shared(&Bs[n0 + p * 16 + lrow][lkof]);

  uint4 va[4];
  float4 va32[8];
  float4 vb[8];
  if (ABF16) {
    const __nv_bfloat16* A = (const __nv_bfloat16*)Av;
#pragma unroll
    for (int i = 0; i < 4; i++) {
      const int f = tid + i * 256;
      va[i] = *(const uint4*)&A[(size_t)(row0 + (f >> 3)) * K + (f & 7) * 8];
    }
  } else {
    const float* A = (const float*)Av;
#pragma unroll
    for (int i = 0; i < 8; i++) {
      const int f = tid + i * 256;
      va32[i] = *(const float4*)&A[(size_t)(row0 + (f >> 4)) * K + (f & 15) * 4];
    }
  }
#pragma unroll
  for (int i = 0; i < 4; i++) {
    const int g = tid + i * 256;
    const int n4 = g & 31, k2 = g >> 5;
    vb[2 * i] = *(const float4*)&W[(size_t)(2 * k2) * N + col0 + n4 * 4];
    vb[2 * i + 1] = *(const float4*)&W[(size_t)(2 * k2 + 1) * N + col0 + n4 * 4];
  }

  for (int kt = 0; kt < K; kt += 64) {
    __syncthreads();
    if (ABF16) {
#pragma unroll
      for (int i = 0; i < 4; i++) {
        const int f = tid + i * 256;
        *(uint4*)&As[f >> 3][(f & 7) * 4] = va[i];
      }
    } else {
#pragma unroll
      for (int i = 0; i < 8; i++) {
        const int f = tid + i * 256;
        const int row = f >> 4, k4 = f & 15;
        As[row][k4 * 2 + 0] = packbf(va32[i].x, va32[i].y);
        As[row][k4 * 2 + 1] = packbf(va32[i].z, va32[i].w);
      }
    }
#pragma unroll
    for (int i = 0; i < 4; i++) {
      const int g = tid + i * 256;
      const int n4 = g & 31, k2 = g >> 5;
      const float4 lo = vb[2 * i], hi = vb[2 * i + 1];
      Bs[n4 * 4 + 0][k2] = packbf(lo.x, hi.x);
      Bs[n4 * 4 + 1][k2] = packbf(lo.y, hi.y);
      Bs[n4 * 4 + 2][k2] = packbf(lo.z, hi.z);
      Bs[n4 * 4 + 3][k2] = packbf(lo.w, hi.w);
    }
    __syncthreads();
    if (kt + 64 < K) {
      if (ABF16) {
        const __nv_bfloat16* A = (const __nv_bfloat16*)Av;
#pragma unroll
        for (int i = 0; i < 4; i++) {
          const int f = tid + i * 256;
          va[i] = *(const uint4*)&A[(size_t)(row0 + (f >> 3)) * K + kt + 64 +
                                    (f & 7) * 8];
        }
      } else {
        const float* A = (const float*)Av;
#pragma unroll
        for (int i = 0; i < 8; i++) {
          const int f = tid + i * 256;
          va32[i] = *(const float4*)&A[(size_t)(row0 + (f >> 4)) * K + kt + 64 +
                                       (f & 15) * 4];
        }
      }
#pragma unroll
      for (int i = 0; i < 4; i++) {
        const int g = tid + i * 256;
        const int n4 = g & 31, k2 = g >> 5;
        vb[2 * i] =
            *(const float4*)&W[(size_t)(kt + 64 + 2 * k2) * N + col0 + n4 * 4];
        vb[2 * i + 1] = *(const float4*)&W[(size_t)(kt + 64 + 2 * k2 + 1) * N +
                                           col0 + n4 * 4];
      }
    }
#pragma unroll
    for (int ck = 0; ck < 4; ck++) {
      const uint32_t koff = ck * 32;
      uint32_t af[2][4], bf[8][2];
#pragma unroll
      for (int mf = 0; mf < 2; mf++)
        ldsm4(af[mf][0], af[mf][1], af[mf][2], af[mf][3], aB[mf] + koff);
#pragma unroll
      for (int p = 0; p < 4; p++)
        ldsm4(bf[2 * p][0], bf[2 * p + 1][0], bf[2 * p][1], bf[2 * p + 1][1],
              bB[p] + koff);
#pragma unroll
      for (int mf = 0; mf < 2; mf++)
#pragma unroll
        for (int nf = 0; nf < 8; nf++) mma_bf16(acc[mf][nf], af[mf], bf[nf]);
    }
  }

  if (!ATTN) {
#pragma unroll
    for (int mf = 0; mf < 2; mf++) {
#pragma unroll
      for (int nf = 0; nf < 8; nf++) {
        const int cc = col0 + n0 + nf * 8 + c4 * 2;
        const float b0 = bias[cc], b1 = bias[cc + 1];
        const int rr = row0 + m0 + mf * 16 + r;
        *(uint32_t*)&C[(size_t)rr * N + cc] =
            packbf(acc[mf][nf][0] + b0, acc[mf][nf][1] + b1);
        *(uint32_t*)&C[(size_t)(rr + 8) * N + cc] =
            packbf(acc[mf][nf][2] + b0, acc[mf][nf][3] + b1);
      }
    }
  } else {
    float s0[2] = {0.f, 0.f}, s1[2] = {0.f, 0.f};
#pragma unroll
    for (int mf = 0; mf < 2; mf++) {
#pragma unroll
      for (int nf = 0; nf < 8; nf++) {
        const int cc = col0 + n0 + nf * 8 + c4 * 2;
        const float b0 = bias[cc], b1 = bias[cc + 1];
        s0[mf] += tanhf(acc[mf][nf][0] + b0) + tanhf(acc[mf][nf][1] + b1);
        s1[mf] += tanhf(acc[mf][nf][2] + b0) + tanhf(acc[mf][nf][3] + b1);
      }
#pragma unroll
      for (int o = 1; o < 4; o <<= 1) {
        s0[mf] += __shfl_xor_sync(0xFFFFFFFFu, s0[mf], o);
        s1[mf] += __shfl_xor_sync(0xFFFFFFFFu, s1[mf], o);
      }
    }
    if (c4 == 0) {
#pragma unroll
      for (int mf = 0; mf < 2; mf++) {
        srow[m0 + mf * 16 + r][wn] = s0[mf];
        srow[m0 + mf * 16 + 8 + r][wn] = s1[mf];
      }
    }
    __syncthreads();
    if (tid < 128)
      spart[(size_t)blockIdx.x * MR_ + row0 + tid] = srow[tid][0] + srow[tid][1];
  }
}

// ---------------- persistent LSTM scan (R12 structure, bf16 xz) -------------
// Grid 128 = 8 groups (mb) x 16 blocks (jb). Block: 16 batches x 32 h-cols.
// Arrival-ordered peer STAGING (coalesced uint4) + ldmatrix fragment loads.
#define SCPAD 260
#define ZPAD 33
#define SMEM_SCAN ((128 * SCPAD + 16 * SCPAD) * 4 + 4 * 16 * ZPAD * 4)

__global__ __launch_bounds__(256) void lstm_scan(
    const __nv_bfloat16* __restrict__ xz, const float* __restrict__ U,
    __nv_bfloat16* __restrict__ seqbf, float* __restrict__ seq32,
    __nv_bfloat16* __restrict__ hbuf,
    const float* __restrict__ bng, const float* __restrict__ bnb,
    const float* __restrict__ bnm, const float* __restrict__ bnv,
    int apply_bn, int w32) {
  extern __shared__ uint32_t dsm[];
  uint32_t(*Us)[SCPAD] = (uint32_t(*)[SCPAD])dsm;                  // [128][260]
  uint32_t(*Asm)[SCPAD] = (uint32_t(*)[SCPAD])(dsm + 128 * SCPAD); // [16][260]
  float* zbuf = (float*)(dsm + 144 * SCPAD);                       // [4][16][33]

  const int bid = blockIdx.x, tid = threadIdx.x;
  const int mb = bid >> 4, jb = bid & 15;
  const int j0 = jb * 32, b0g = mb * 16;
  const int gbase = mb * 16;
  const int warp = tid >> 5, lane = tid & 31;
  const int q = warp >> 1, half = warp & 1;
  const int r = lane >> 2, c4 = lane & 3;
  const int quad = lane >> 3, l7 = lane & 7;
  const int lrow = l7 + ((quad & 1) << 3);
  const int lkof = (quad >> 1) << 2;

  // stage U tile once: Us[n][k2], n = q*32 + local col, bf16x2 in k
#pragma unroll
  for (int i = 0; i < 32; i++) {
    const int g = tid + i * 256;
    const int n4 = g & 31, k2 = g >> 5;
    const int qq = n4 >> 3, cg = n4 & 7;
    const int gcol = qq * 512 + j0 + cg * 4;
    const float4 lo = *(const float4*)&U[(size_t)(2 * k2) * G_ + gcol];
    const float4 hi = *(const float4*)&U[(size_t)(2 * k2 + 1) * G_ + gcol];
    Us[n4 * 4 + 0][k2] = packbf(lo.x, hi.x);
    Us[n4 * 4 + 1][k2] = packbf(lo.y, hi.y);
    Us[n4 * 4 + 2][k2] = packbf(lo.z, hi.z);
    Us[n4 * 4 + 3][k2] = packbf(lo.w, hi.w);
  }

  const uint32_t aBase = (uint32_t)__cvta_generic_to_shared(&Asm[lrow][lkof]);
  const uint32_t bBase = (uint32_t)__cvta_generic_to_shared(
      &Us[q * 32 + half * 16 + lrow][lkof]);

  // per-thread gate-cell ownership: 16 batches x 32 cols, 2 cols/thread
  const int bl = tid >> 4, jj = (tid & 15) * 2;
  const int bg = b0g + bl, jgl = j0 + jj;
  float c1 = 0.f, c2 = 0.f;
  float scl1 = 1.f, sft1 = 0.f, scl2 = 1.f, sft2 = 0.f;
  if (apply_bn) {
    scl1 = rsqrtf(bnv[jgl] + EPS_) * bng[jgl];
    sft1 = bnb[jgl] - bnm[jgl] * scl1;
    scl2 = rsqrtf(bnv[jgl + 1] + EPS_) * bng[jgl + 1];
    sft2 = bnb[jgl + 1] - bnm[jgl + 1] * scl2;
  }
  __nv_bfloat16* hw_base = hbuf + (size_t)bg * H_ + jgl;

  // staging roles: warp handles peers 2*warp + (lane>>4); 16 lanes per peer
  const int peer = warp * 2 + (lane >> 4);
  const int pl = lane & 15;
  const int* peer_flag = &g_flags[(gbase + peer) * 32];

  // xz (bf16) prefetch pointers per mma C-fragment layout
  const __nv_bfloat16* xzb1 =
      xz + ((size_t)(b0g + r) * T_) * G_ + q * 512 + j0 + half * 16;
  const __nv_bfloat16* xzb2 =
      xz + ((size_t)(b0g + 8 + r) * T_) * G_ + q * 512 + j0 + half * 16;
  uint32_t xp[4];
#pragma unroll
  for (int nf = 0; nf < 2; nf++) {
    const int cA = nf * 8 + c4 * 2;
    xp[nf * 2 + 0] = __ldg((const uint32_t*)(xzb1 + cA));
    xp[nf * 2 + 1] = __ldg((const uint32_t*)(xzb2 + cA));
  }

  int ls = 0;
  if (tid == 0) {
    ls = g_bar_sense;
    g_flags[bid * 32] = 0;
  }
  grid_bar_atomic(ls);

  for (int t = 0; t < T_; t++) {
    float accA[2][4], accB[2][4];
#pragma unroll
    for (int i = 0; i < 2; i++)
#pragma unroll
      for (int j = 0; j < 4; j++) { accA[i][j] = 0.f; accB[i][j] = 0.f; }

    if (t > 0) {
      const __nv_bfloat16* hsrc = hbuf + (size_t)(t & 1) * B_ * H_;
      {
        int v;
        do {
          asm volatile("ld.acquire.gpu.global.b32 %0, [%1];"
                       : "=r"(v) : "l"(peer_flag));
        } while (v < t);
      }
      const uint4* src =
          (const uint4*)&hsrc[(size_t)(b0g + pl) * H_ + peer * 32];
      const uint4 v0 = __ldcg(src + 0);
      const uint4 v1 = __ldcg(src + 1);
      const uint4 v2 = __ldcg(src + 2);
      const uint4 v3 = __ldcg(src + 3);
      uint32_t* dst = &Asm[pl][peer * 16];
      *(uint4*)(dst + 0) = v0;
      *(uint4*)(dst + 4) = v1;
      *(uint4*)(dst + 8) = v2;
      *(uint4*)(dst + 12) = v3;
      __syncthreads();  // all peers confirmed + staged (group barrier)

#pragma unroll 8
      for (int ck = 0; ck < 16; ck++) {
        const uint32_t koff = (uint32_t)ck * 32;
        uint32_t af[4], b00, b10, b01, b11;
        ldsm4(af[0], af[1], af[2], af[3], aBase + koff);
        ldsm4(b00, b10, b01, b11, bBase + koff);
        uint32_t bf0[2] = {b00, b01}, bf1[2] = {b10, b11};
        mma_bf16(accA[0], af, bf0);
        mma_bf16(accA[1], af, bf1);
      }
#pragma unroll 8
      for (int ck = 16; ck < 32; ck++) {
        const uint32_t koff = (uint32_t)ck * 32;
        uint32_t af[4], b00, b10, b01, b11;
        ldsm4(af[0], af[1], af[2], af[3], aBase + koff);
        ldsm4(b00, b10, b01, b11, bBase + koff);
        uint32_t bf0[2] = {b00, b01}, bf1[2] = {b10, b11};
        mma_bf16(accB[0], af, bf0);
        mma_bf16(accB[1], af, bf1);
      }
    }

    // z = acc + xz -> zbuf[q][batch][col32]
#pragma unroll
    for (int nf = 0; nf < 2; nf++) {
      const int col = half * 16 + nf * 8 + c4 * 2;
      float* zb = zbuf + (size_t)q * 16 * ZPAD;
      const float2 x1 = unpackbf(xp[nf * 2 + 0]);
      const float2 x2 = unpackbf(xp[nf * 2 + 1]);
      zb[r * ZPAD + col] = accA[nf][0] + accB[nf][0] + x1.x;
      zb[r * ZPAD + col + 1] = accA[nf][1] + accB[nf][1] + x1.y;
      zb[(r + 8) * ZPAD + col] = accA[nf][2] + accB[nf][2] + x2.x;
      zb[(r + 8) * ZPAD + col + 1] = accA[nf][3] + accB[nf][3] + x2.y;
    }
    __syncthreads();

    const float zi1 = zbuf[(0 * 16 + bl) * ZPAD + jj];
    const float zi2 = zbuf[(0 * 16 + bl) * ZPAD + jj + 1];
    const float zf1 = zbuf[(1 * 16 + bl) * ZPAD + jj];
    const float zf2 = zbuf[(1 * 16 + bl) * ZPAD + jj + 1];
    const float zg1 = zbuf[(2 * 16 + bl) * ZPAD + jj];
    const float zg2 = zbuf[(2 * 16 + bl) * ZPAD + jj + 1];
    const float zo1 = zbuf[(3 * 16 + bl) * ZPAD + jj];
    const float zo2 = zbuf[(3 * 16 + bl) * ZPAD + jj + 1];

    if (t + 1 < T_) {
#pragma unroll
      for (int nf = 0; nf < 2; nf++) {
        const int cA = nf * 8 + c4 * 2;
        xp[nf * 2 + 0] =
            __ldg((const uint32_t*)(xzb1 + (size_t)(t + 1) * G_ + cA));
        xp[nf * 2 + 1] =
            __ldg((const uint32_t*)(xzb2 + (size_t)(t + 1) * G_ + cA));
      }
    }

    const float i1 = siga(zi1), f1 = siga(zf1), g1 = tanha(zg1), o1 = siga(zo1);
    c1 = f1 * c1 + i1 * g1;
    const float h1 = o1 * tanha(c1);
    const float i2 = siga(zi2), f2 = siga(zf2), g2 = tanha(zg2), o2 = siga(zo2);
    c2 = f2 * c2 + i2 * g2;
    const float h2 = o2 * tanha(c2);

    *(uint32_t*)(hw_base + (size_t)((t + 1) & 1) * B_ * H_) = packbf(h1, h2);
    bar_release(t + 1);

    const float s1v = apply_bn ? (h1 * scl1 + sft1) : h1;
    const float s2v = apply_bn ? (h2 * scl2 + sft2) : h2;
    *(uint32_t*)&seqbf[((size_t)bg * T_ + t) * H_ + jgl] = packbf(s1v, s2v);
    if (w32)
      *(float2*)&seq32[((size_t)bg * T_ + t) * H_ + jgl] = make_float2(s1v, s2v);
  }
}

// ---------------- attention tail / head -------------------------------------
__global__ void rowsum_final(const float* __restrict__ sp,
                             float* __restrict__ s) {
  const int i = blockIdx.x * blockDim.x + threadIdx.x;
  s[i] = sp[i] + sp[MR_ + i] + sp[2 * MR_ + i] + sp[3 * MR_ + i];
}

__global__ __launch_bounds__(512) void softmax_kernel(float* __restrict__ s) {
  __shared__ float red[T_];
  const int b = blockIdx.x, t = threadIdx.x;
  const float v = s[b * T_ + t];
  red[t] = v;
  __syncthreads();
  for (int o = 256; o; o >>= 1) {
    if (t < o) red[t] = fmaxf(red[t], red[t + o]);
    __syncthreads();
  }
  const float m = red[0];
  __syncthreads();
  const float ev = expf(v - m);
  red[t] = ev;
  __syncthreads();
  for (int o = 256; o; o >>= 1) {
    if (t < o) red[t] += red[t + o];
    __syncthreads();
  }
  s[b * T_ + t] = ev / red[0];
}

__global__ __launch_bounds__(512) void pool_kernel(const float* __restrict__ seq,
                                                   const float* __restrict__ a,
                                                   float* __restrict__ pool) {
  const int b = blockIdx.x, d = threadIdx.x;
  const float* p = seq + (size_t)b * T_ * H_ + d;
  const float* ap = a + b * T_;
  float acc = 0.f;
  for (int t = 0; t < T_; t++) acc += ap[t] * p[(size_t)t * H_];
  pool[b * H_ + d] = acc * (1.0f / T_);
}

__global__ __launch_bounds__(128) void head_kernel(
    const float* __restrict__ pool,
    const float* __restrict__ Wd1, const float* __restrict__ bd1,
    const float* __restrict__ bng, const float* __restrict__ bnb,
    const float* __restrict__ bnm, const float* __restrict__ bnv,
    const float* __restrict__ Wd2, const float* __restrict__ bd2,
    const float* __restrict__ Wd3, const float* __restrict__ bd3,
    float* __restrict__ out) {
  __shared__ float sp[H_];
  __shared__ float d1[128];
  __shared__ float d2[64];
  const int b = blockIdx.x, t = threadIdx.x;
  for (int i = t; i < H_; i += 128) sp[i] = pool[b * H_ + i];
  __syncthreads();
  {
    float acc = bd1[t];
    for (int k = 0; k < H_; k++) acc += sp[k] * Wd1[k * 128 + t];
    acc = fmaxf(acc, 0.f);
    acc = (acc - bnm[t]) * rsqrtf(bnv[t] + EPS_) * bng[t] + bnb[t];
    d1[t] = acc;
  }
  __syncthreads();
  if (t < 64) {
    float acc = bd2[t];
    for (int k = 0; k < 128; k++) acc += d1[k] * Wd2[k * 64 + t];
    d2[t] = fmaxf(acc, 0.f);
  }
  __syncthreads();
  if (t < 5) {
    float acc = bd3[t];
    for (int k = 0; k < 64; k++) acc += d2[k] * Wd3[k * 5 + t];
    out[b * 5 + t] = acc;
  }
}

// ---------------- launch ----------------------------------------------------
extern "C" void kernel_launch(void* const* d_in, const int* in_sizes, int n_in,
                              void* d_out, int out_size) {
  (void)out_size;
  static const int sig_map[30] = {0, 1, 2, 3, 8, 9, 10, 15, 16, 17,
                                  4, 5, 6, 7, 11, 12, 13, 14, 22, 23,
                                  24, 25, 18, 19, 20, 21, 26, 27, 28, 29};
  const int setup_order = (n_in >= 5 && in_sizes[4] == 1048576) ? 1 : 0;
  const float* in[30];
  for (int i = 0; i < 30; i++)
    in[i] = (const float*)d_in[setup_order ? i : sig_map[i]];

  const float* x = in[0];
  const float* Wl[3] = {in[1], in[4], in[7]};
  const float* Ul[3] = {in[2], in[5], in[8]};
  const float* bl[3] = {in[3], in[6], in[9]};
  const float* bng[3] = {in[10], in[14], in[18]};
  const float* bnb[3] = {in[11], in[15], in[19]};
  const float* bnm[3] = {in[12], in[16], in[20]};
  const float* bnv[3] = {in[13], in[17], in[21]};
  const float* Wa = in[22];  const float* ba = in[23];
  const float* Wd1 = in[24]; const float* bd1 = in[25];
  const float* Wd2 = in[26]; const float* bd2 = in[27];
  const float* Wd3 = in[28]; const float* bd3 = in[29];

  float *seq32, *spart, *s, *pool;
  __nv_bfloat16 *xz, *seqA, *seqB, *hbuf;
  cudaGetSymbolAddress((void**)&xz, g_xz);
  cudaGetSymbolAddress((void**)&seqA, g_seqA);
  cudaGetSymbolAddress((void**)&seqB, g_seqB);
  cudaGetSymbolAddress((void**)&seq32, g_seq32);
  cudaGetSymbolAddress((void**)&hbuf, g_hbuf);
  cudaGetSymbolAddress((void**)&spart, g_spart);
  cudaGetSymbolAddress((void**)&s, g_s);
  cudaGetSymbolAddress((void**)&pool, g_pool);

  cudaFuncSetAttribute(lstm_scan, cudaFuncAttributeMaxDynamicSharedMemorySize,
                       SMEM_SCAN);

  gemm_bf16k<false, false><<<dim3(G_ / 128, MR_ / 128), 256>>>(
      x, Wl[0], bl[0], xz, nullptr, D_, G_);
  lstm_scan<<<NBLK_, 256, SMEM_SCAN>>>(xz, Ul[0], seqA, seq32, hbuf,
                                       bng[0], bnb[0], bnm[0], bnv[0], 1, 0);
  gemm_bf16k<true, false><<<dim3(G_ / 128, MR_ / 128), 256>>>(
      seqA, Wl[1], bl[1], xz, nullptr, H_, G_);
  lstm_scan<<<NBLK_, 256, SMEM_SCAN>>>(xz, Ul[1], seqB, seq32, hbuf,
                                       bng[1], bnb[1], bnm[1], bnv[1], 1, 0);
  gemm_bf16k<true, false><<<dim3(G_ / 128, MR_ / 128), 256>>>(
      seqB, Wl[2], bl[2], xz, nullptr, H_, G_);
  lstm_scan<<<NBLK_, 256, SMEM_SCAN>>>(xz, Ul[2], seqA, seq32, hbuf,
                                       bng[2], bnb[2], bnm[2], bnv[2], 0, 1);

  gemm_bf16k<true, true><<<dim3(H_ / 128, MR_ / 128), 256>>>(
      seqA, Wa, ba, nullptr, spart, H_, H_);
  rowsum_final<<<MR_ / 256, 256>>>(spart, s);
  softmax_kernel<<<B_, T_>>>(s);
  pool_kernel<<<B_, H_>>>(seq32, s, pool);
  head_kernel<<<B_, 128>>>(pool, Wd1, bd1, bng[2], bnb[2], bnm[2], bnv[2],
                           Wd2, bd2, Wd3, bd3, (float*)d_out);
}

// round 16
// speedup vs baseline: 2.4915x; 1.0267x over previous
#include <cuda_runtime.h>
#include <cuda_bf16.h>
#include <math.h>
#include <stdint.h>

#define B_ 128
#define T_ 512
#define D_ 128
#define H_ 512
#define G_ 2048          // 4*H
#define EPS_ 1e-3f
#define NBLK_ 128
#define MR_ (B_ * T_)    // 65536

// ---------------- scratch (static device allocations) -----------------------
__device__ __align__(16) __nv_bfloat16 g_xz[(size_t)B_ * T_ * G_];  // bf16 xz
__device__ __align__(16) __nv_bfloat16 g_seqA[(size_t)B_ * T_ * H_];
__device__ __align__(16) __nv_bfloat16 g_seqB[(size_t)B_ * T_ * H_];
// h double buffer, COLBLOCK-MAJOR: [2][16 colblk][128 batch][32 cols]
__device__ __align__(16) __nv_bfloat16 g_hbuf[2 * B_ * H_];
__device__ __align__(16) float g_spart[4 * MR_];
__device__ __align__(16) float g_s[MR_];
__device__ __align__(16) float g_pool[B_ * H_];
__device__ volatile int g_bar_count;
__device__ volatile int g_bar_sense;
__device__ int g_flags[NBLK_ * 32];  // one 128B line per block

// ---------------- helpers ----------------------------------------------------
__device__ __forceinline__ uint32_t packbf(float lo, float hi) {
  __nv_bfloat162 v = __floats2bfloat162_rn(lo, hi);
  return *(uint32_t*)&v;
}
__device__ __forceinline__ float2 unpackbf(uint32_t u) {
  __nv_bfloat162 v = *(__nv_bfloat162*)&u;
  return __bfloat1622float2(v);
}
__device__ __forceinline__ void mma_bf16(float* d, const uint32_t* a,
                                         const uint32_t* b) {
  asm("mma.sync.aligned.m16n8k16.row.col.f32.bf16.bf16.f32 "
      "{%0,%1,%2,%3}, {%4,%5,%6,%7}, {%8,%9}, {%0,%1,%2,%3};"
      : "+f"(d[0]), "+f"(d[1]), "+f"(d[2]), "+f"(d[3])
      : "r"(a[0]), "r"(a[1]), "r"(a[2]), "r"(a[3]), "r"(b[0]), "r"(b[1]));
}
__device__ __forceinline__ void ldsm4(uint32_t& r0, uint32_t& r1, uint32_t& r2,
                                      uint32_t& r3, uint32_t addr) {
  asm volatile(
      "ldmatrix.sync.aligned.m8n8.x4.shared.b16 {%0,%1,%2,%3}, [%4];"
      : "=r"(r0), "=r"(r1), "=r"(r2), "=r"(r3) : "r"(addr));
}
__device__ __forceinline__ float tanha(float x) {
  float y;
  asm("tanh.approx.f32 %0, %1;" : "=f"(y) : "f"(x));
  return y;
}
__device__ __forceinline__ float siga(float x) {
  return fmaf(tanha(0.5f * x), 0.5f, 0.5f);
}

__device__ __forceinline__ void grid_bar_atomic(int& ls) {
  __syncthreads();
  if (threadIdx.x == 0) {
    __threadfence();
    const int s = ls ^ 1;
    ls = s;
    if (atomicAdd((int*)&g_bar_count, 1) == NBLK_ - 1) {
      g_bar_count = 0;
      __threadfence();
      g_bar_sense = s;
    } else {
      while (g_bar_sense != s) { }
    }
    __threadfence();
  }
  __syncthreads();
}

__device__ __forceinline__ void bar_release(int phase) {
  __syncthreads();
  if (threadIdx.x == 0) {
    asm volatile("st.release.gpu.global.b32 [%0], %1;"
                 :: "l"(&g_flags[blockIdx.x * 32]), "r"(phase) : "memory");
  }
}

// ---------------- bf16 tensor GEMM: Cbf16 = A[M,K]@W[K,N] + bias ------------
template <bool ABF16, bool ATTN>
__global__ __launch_bounds__(256) void gemm_bf16k(
    const void* __restrict__ Av, const float* __restrict__ W,
    const float* __restrict__ bias, __nv_bfloat16* __restrict__ C,
    float* __restrict__ spart, int K, int N) {
  __shared__ uint32_t As[128][36];
  __shared__ uint32_t Bs[128][36];
  __shared__ float srow[128][2];
  const int tid = threadIdx.x;
  const int warp = tid >> 5, lane = tid & 31;
  const int wm = warp >> 1, wn = warp & 1;
  const int m0 = wm * 32, n0 = wn * 64;
  const int r = lane >> 2, c4 = lane & 3;
  const int row0 = blockIdx.y * 128, col0 = blockIdx.x * 128;
  const int quad = lane >> 3, l7 = lane & 7;
  const int lrow = l7 + ((quad & 1) << 3);
  const int lkof = (quad >> 1) << 2;

  float acc[2][8][4];
#pragma unroll
  for (int i = 0; i < 2; i++)
#pragma unroll
    for (int j = 0; j < 8; j++)
#pragma unroll
      for (int k = 0; k < 4; k++) acc[i][j][k] = 0.f;

  uint32_t aB[2], bB[4];
#pragma unroll
  for (int mf = 0; mf < 2; mf++)
    aB[mf] = (uint32_t)__cvta_generic_to_shared(&As[m0 + mf * 16 + lrow][lkof]);
#pragma unroll
  for (int p = 0; p < 4; p++)
    bB[p] = (uint32_t)__cvta_generic_to_shared(&Bs[n0 + p * 16 + lrow][lkof]);

  uint4 va[4];
  float4 va32[8];
  float4 vb[8];
  if (ABF16) {
    const __nv_bfloat16* A = (const __nv_bfloat16*)Av;
#pragma unroll
    for (int i = 0; i < 4; i++) {
      const int f = tid + i * 256;
      va[i] = *(const uint4*)&A[(size_t)(row0 + (f >> 3)) * K + (f & 7) * 8];
    }
  } else {
    const float* A = (const float*)Av;
#pragma unroll
    for (int i = 0; i < 8; i++) {
      const int f = tid + i * 256;
      va32[i] = *(const float4*)&A[(size_t)(row0 + (f >> 4)) * K + (f & 15) * 4];
    }
  }
#pragma unroll
  for (int i = 0; i < 4; i++) {
    const int g = tid + i * 256;
    const int n4 = g & 31, k2 = g >> 5;
    vb[2 * i] = *(const float4*)&W[(size_t)(2 * k2) * N + col0 + n4 * 4];
    vb[2 * i + 1] = *(const float4*)&W[(size_t)(2 * k2 + 1) * N + col0 + n4 * 4];
  }

  for (int kt = 0; kt < K; kt += 64) {
    __syncthreads();
    if (ABF16) {
#pragma unroll
      for (int i = 0; i < 4; i++) {
        const int f = tid + i * 256;
        *(uint4*)&As[f >> 3][(f & 7) * 4] = va[i];
      }
    } else {
#pragma unroll
      for (int i = 0; i < 8; i++) {
        const int f = tid + i * 256;
        const int row = f >> 4, k4 = f & 15;
        As[row][k4 * 2 + 0] = packbf(va32[i].x, va32[i].y);
        As[row][k4 * 2 + 1] = packbf(va32[i].z, va32[i].w);
      }
    }
#pragma unroll
    for (int i = 0; i < 4; i++) {
      const int g = tid + i * 256;
      const int n4 = g & 31, k2 = g >> 5;
      const float4 lo = vb[2 * i], hi = vb[2 * i + 1];
      Bs[n4 * 4 + 0][k2] = packbf(lo.x, hi.x);
      Bs[n4 * 4 + 1][k2] = packbf(lo.y, hi.y);
      Bs[n4 * 4 + 2][k2] = packbf(lo.z, hi.z);
      Bs[n4 * 4 + 3][k2] = packbf(lo.w, hi.w);
    }
    __syncthreads();
    if (kt + 64 < K) {
      if (ABF16) {
        const __nv_bfloat16* A = (const __nv_bfloat16*)Av;
#pragma unroll
        for (int i = 0; i < 4; i++) {
          const int f = tid + i * 256;
          va[i] = *(const uint4*)&A[(size_t)(row0 + (f >> 3)) * K + kt + 64 +
                                    (f & 7) * 8];
        }
      } else {
        const float* A = (const float*)Av;
#pragma unroll
        for (int i = 0; i < 8; i++) {
          const int f = tid + i * 256;
          va32[i] = *(const float4*)&A[(size_t)(row0 + (f >> 4)) * K + kt + 64 +
                                       (f & 15) * 4];
        }
      }
#pragma unroll
      for (int i = 0; i < 4; i++) {
        const int g = tid + i * 256;
        const int n4 = g & 31, k2 = g >> 5;
        vb[2 * i] =
            *(const float4*)&W[(size_t)(kt + 64 + 2 * k2) * N + col0 + n4 * 4];
        vb[2 * i + 1] = *(const float4*)&W[(size_t)(kt + 64 + 2 * k2 + 1) * N +
                                           col0 + n4 * 4];
      }
    }
#pragma unroll
    for (int ck = 0; ck < 4; ck++) {
      const uint32_t koff = ck * 32;
      uint32_t af[2][4], bf[8][2];
#pragma unroll
      for (int mf = 0; mf < 2; mf++)
        ldsm4(af[mf][0], af[mf][1], af[mf][2], af[mf][3], aB[mf] + koff);
#pragma unroll
      for (int p = 0; p < 4; p++)
        ldsm4(bf[2 * p][0], bf[2 * p + 1][0], bf[2 * p][1], bf[2 * p + 1][1],
              bB[p] + koff);
#pragma unroll
      for (int mf = 0; mf < 2; mf++)
#pragma unroll
        for (int nf = 0; nf < 8; nf++) mma_bf16(acc[mf][nf], af[mf], bf[nf]);
    }
  }

  if (!ATTN) {
#pragma unroll
    for (int mf = 0; mf < 2; mf++) {
#pragma unroll
      for (int nf = 0; nf < 8; nf++) {
        const int cc = col0 + n0 + nf * 8 + c4 * 2;
        const float b0 = bias[cc], b1 = bias[cc + 1];
        const int rr = row0 + m0 + mf * 16 + r;
        *(uint32_t*)&C[(size_t)rr * N + cc] =
            packbf(acc[mf][nf][0] + b0, acc[mf][nf][1] + b1);
        *(uint32_t*)&C[(size_t)(rr + 8) * N + cc] =
            packbf(acc[mf][nf][2] + b0, acc[mf][nf][3] + b1);
      }
    }
  } else {
    float s0[2] = {0.f, 0.f}, s1[2] = {0.f, 0.f};
#pragma unroll
    for (int mf = 0; mf < 2; mf++) {
#pragma unroll
      for (int nf = 0; nf < 8; nf++) {
        const int cc = col0 + n0 + nf * 8 + c4 * 2;
        const float b0 = bias[cc], b1 = bias[cc + 1];
        s0[mf] += tanhf(acc[mf][nf][0] + b0) + tanhf(acc[mf][nf][1] + b1);
        s1[mf] += tanhf(acc[mf][nf][2] + b0) + tanhf(acc[mf][nf][3] + b1);
      }
#pragma unroll
      for (int o = 1; o < 4; o <<= 1) {
        s0[mf] += __shfl_xor_sync(0xFFFFFFFFu, s0[mf], o);
        s1[mf] += __shfl_xor_sync(0xFFFFFFFFu, s1[mf], o);
      }
    }
    if (c4 == 0) {
#pragma unroll
      for (int mf = 0; mf < 2; mf++) {
        srow[m0 + mf * 16 + r][wn] = s0[mf];
        srow[m0 + mf * 16 + 8 + r][wn] = s1[mf];
      }
    }
    __syncthreads();
    if (tid < 128)
      spart[(size_t)blockIdx.x * MR_ + row0 + tid] = srow[tid][0] + srow[tid][1];
  }
}

// ---------------- persistent LSTM scan --------------------------------------
// Grid 128 = 8 groups (mb) x 16 blocks (jb). Block: 16 batches x 32 h-cols.
// h buffer is COLBLOCK-MAJOR [2][jb][batch][32]: a peer's slice for one batch
// group is 1KB CONTIGUOUS -> fully coalesced staging; producer stores are
// 128B-contiguous per warp. Asm layout and mma wiring unchanged.
#define SCPAD 260
#define ZPAD 33
#define SMEM_SCAN ((128 * SCPAD + 16 * SCPAD) * 4 + 4 * 16 * ZPAD * 4)

__global__ __launch_bounds__(256) void lstm_scan(
    const __nv_bfloat16* __restrict__ xz, const float* __restrict__ U,
    __nv_bfloat16* __restrict__ seqbf, __nv_bfloat16* __restrict__ hbuf,
    const float* __restrict__ bng, const float* __restrict__ bnb,
    const float* __restrict__ bnm, const float* __restrict__ bnv,
    int apply_bn) {
  extern __shared__ uint32_t dsm[];
  uint32_t(*Us)[SCPAD] = (uint32_t(*)[SCPAD])dsm;                  // [128][260]
  uint32_t(*Asm)[SCPAD] = (uint32_t(*)[SCPAD])(dsm + 128 * SCPAD); // [16][260]
  float* zbuf = (float*)(dsm + 144 * SCPAD);                       // [4][16][33]

  const int bid = blockIdx.x, tid = threadIdx.x;
  const int mb = bid >> 4, jb = bid & 15;
  const int j0 = jb * 32, b0g = mb * 16;
  const int gbase = mb * 16;
  const int warp = tid >> 5, lane = tid & 31;
  const int q = warp >> 1, half = warp & 1;
  const int r = lane >> 2, c4 = lane & 3;
  const int quad = lane >> 3, l7 = lane & 7;
  const int lrow = l7 + ((quad & 1) << 3);
  const int lkof = (quad >> 1) << 2;

  // stage U tile once: Us[n][k2], n = q*32 + local col, bf16x2 in k
#pragma unroll
  for (int i = 0; i < 32; i++) {
    const int g = tid + i * 256;
    const int n4 = g & 31, k2 = g >> 5;
    const int qq = n4 >> 3, cg = n4 & 7;
    const int gcol = qq * 512 + j0 + cg * 4;
    const float4 lo = *(const float4*)&U[(size_t)(2 * k2) * G_ + gcol];
    const float4 hi = *(const float4*)&U[(size_t)(2 * k2 + 1) * G_ + gcol];
    Us[n4 * 4 + 0][k2] = packbf(lo.x, hi.x);
    Us[n4 * 4 + 1][k2] = packbf(lo.y, hi.y);
    Us[n4 * 4 + 2][k2] = packbf(lo.z, hi.z);
    Us[n4 * 4 + 3][k2] = packbf(lo.w, hi.w);
  }

  const uint32_t aBase = (uint32_t)__cvta_generic_to_shared(&Asm[lrow][lkof]);
  const uint32_t bBase = (uint32_t)__cvta_generic_to_shared(
      &Us[q * 32 + half * 16 + lrow][lkof]);

  // per-thread gate-cell ownership: 16 batches x 32 cols, 2 cols/thread
  const int bl = tid >> 4, jj = (tid & 15) * 2;
  const int bg = b0g + bl, jgl = j0 + jj;
  float c1 = 0.f, c2 = 0.f;
  float scl1 = 1.f, sft1 = 0.f, scl2 = 1.f, sft2 = 0.f;
  if (apply_bn) {
    scl1 = rsqrtf(bnv[jgl] + EPS_) * bng[jgl];
    sft1 = bnb[jgl] - bnm[jgl] * scl1;
    scl2 = rsqrtf(bnv[jgl + 1] + EPS_) * bng[jgl + 1];
    sft2 = bnb[jgl + 1] - bnm[jgl + 1] * scl2;
  }
  // producer h address, colblock-major: [jb][batch][32]
  __nv_bfloat16* hw_base = hbuf + (size_t)jb * B_ * 32 + bg * 32 + jj;

  // staging roles: warp handles peers 2*warp + (lane>>4); 16 lanes per peer
  const int peer = warp * 2 + (lane >> 4);
  const int pl = lane & 15;
  const int* peer_flag = &g_flags[(gbase + peer) * 32];

  // xz (bf16) prefetch pointers per mma C-fragment layout
  const __nv_bfloat16* xzb1 =
      xz + ((size_t)(b0g + r) * T_) * G_ + q * 512 + j0 + half * 16;
  const __nv_bfloat16* xzb2 =
      xz + ((size_t)(b0g + 8 + r) * T_) * G_ + q * 512 + j0 + half * 16;
  uint32_t xp[4];
#pragma unroll
  for (int nf = 0; nf < 2; nf++) {
    const int cA = nf * 8 + c4 * 2;
    xp[nf * 2 + 0] = __ldg((const uint32_t*)(xzb1 + cA));
    xp[nf * 2 + 1] = __ldg((const uint32_t*)(xzb2 + cA));
  }

  int ls = 0;
  if (tid == 0) {
    ls = g_bar_sense;
    g_flags[bid * 32] = 0;
  }
  grid_bar_atomic(ls);

  for (int t = 0; t < T_; t++) {
    float accA[2][4], accB[2][4];
#pragma unroll
    for (int i = 0; i < 2; i++)
#pragma unroll
      for (int j = 0; j < 4; j++) { accA[i][j] = 0.f; accB[i][j] = 0.f; }

    if (t > 0) {
      const __nv_bfloat16* hsrc = hbuf + (size_t)(t & 1) * B_ * H_;
      {
        int v;
        do {
          asm volatile("ld.acquire.gpu.global.b32 %0, [%1];"
                       : "=r"(v) : "l"(peer_flag));
        } while (v < t);
      }
      // peer slice is CONTIGUOUS 1KB: [peer][b0g..b0g+16][0..32]
      const uint4* src =
          (const uint4*)&hsrc[(size_t)peer * B_ * 32 + (b0g + pl) * 32];
      const uint4 v0 = __ldcg(src + 0);
      const uint4 v1 = __ldcg(src + 1);
      const uint4 v2 = __ldcg(src + 2);
      const uint4 v3 = __ldcg(src + 3);
      uint32_t* dst = &Asm[pl][peer * 16];
      *(uint4*)(dst + 0) = v0;
      *(uint4*)(dst + 4) = v1;
      *(uint4*)(dst + 8) = v2;
      *(uint4*)(dst + 12) = v3;
      __syncthreads();  // all peers confirmed + staged (group barrier)

#pragma unroll 8
      for (int ck = 0; ck < 16; ck++) {
        const uint32_t koff = (uint32_t)ck * 32;
        uint32_t af[4], b00, b10, b01, b11;
        ldsm4(af[0], af[1], af[2], af[3], aBase + koff);
        ldsm4(b00, b10, b01, b11, bBase + koff);
        uint32_t bf0[2] = {b00, b01}, bf1[2] = {b10, b11};
        mma_bf16(accA[0], af, bf0);
        mma_bf16(accA[1], af, bf1);
      }
#pragma unroll 8
      for (int ck = 16; ck < 32; ck++) {
        const uint32_t koff = (uint32_t)ck * 32;
        uint32_t af[4], b00, b10, b01, b11;
        ldsm4(af[0], af[1], af[2], af[3], aBase + koff);
        ldsm4(b00, b10, b01, b11, bBase + koff);
        uint32_t bf0[2] = {b00, b01}, bf1[2] = {b10, b11};
        mma_bf16(accB[0], af, bf0);
        mma_bf16(accB[1], af, bf1);
      }
    }

    // z = acc + xz -> zbuf[q][batch][col32]
#pragma unroll
    for (int nf = 0; nf < 2; nf++) {
      const int col = half * 16 + nf * 8 + c4 * 2;
      float* zb = zbuf + (size_t)q * 16 * ZPAD;
      const float2 x1 = unpackbf(xp[nf * 2 + 0]);
      const float2 x2 = unpackbf(xp[nf * 2 + 1]);
      zb[r * ZPAD + col] = accA[nf][0] + accB[nf][0] + x1.x;
      zb[r * ZPAD + col + 1] = accA[nf][1] + accB[nf][1] + x1.y;
      zb[(r + 8) * ZPAD + col] = accA[nf][2] + accB[nf][2] + x2.x;
      zb[(r + 8) * ZPAD + col + 1] = accA[nf][3] + accB[nf][3] + x2.y;
    }
    __syncthreads();

    const float zi1 = zbuf[(0 * 16 + bl) * ZPAD + jj];
    const float zi2 = zbuf[(0 * 16 + bl) * ZPAD + jj + 1];
    const float zf1 = zbuf[(1 * 16 + bl) * ZPAD + jj];
    const float zf2 = zbuf[(1 * 16 + bl) * ZPAD + jj + 1];
    const float zg1 = zbuf[(2 * 16 + bl) * ZPAD + jj];
    const float zg2 = zbuf[(2 * 16 + bl) * ZPAD + jj + 1];
    const float zo1 = zbuf[(3 * 16 + bl) * ZPAD + jj];
    const float zo2 = zbuf[(3 * 16 + bl) * ZPAD + jj + 1];

    if (t + 1 < T_) {
#pragma unroll
      for (int nf = 0; nf < 2; nf++) {
        const int cA = nf * 8 + c4 * 2;
        xp[nf * 2 + 0] =
            __ldg((const uint32_t*)(xzb1 + (size_t)(t + 1) * G_ + cA));
        xp[nf * 2 + 1] =
            __ldg((const uint32_t*)(xzb2 + (size_t)(t + 1) * G_ + cA));
      }
    }

    const float i1 = siga(zi1), f1 = siga(zf1), g1 = tanha(zg1), o1 = siga(zo1);
    c1 = f1 * c1 + i1 * g1;
    const float h1 = o1 * tanha(c1);
    const float i2 = siga(zi2), f2 = siga(zf2), g2 = tanha(zg2), o2 = siga(zo2);
    c2 = f2 * c2 + i2 * g2;
    const float h2 = o2 * tanha(c2);

    *(uint32_t*)(hw_base + (size_t)((t + 1) & 1) * B_ * H_) = packbf(h1, h2);
    bar_release(t + 1);

    const float s1v = apply_bn ? (h1 * scl1 + sft1) : h1;
    const float s2v = apply_bn ? (h2 * scl2 + sft2) : h2;
    *(uint32_t*)&seqbf[((size_t)bg * T_ + t) * H_ + jgl] = packbf(s1v, s2v);
  }
}

// ---------------- attention tail / head -------------------------------------
__global__ void rowsum_final(const float* __restrict__ sp,
                             float* __restrict__ s) {
  const int i = blockIdx.x * blockDim.x + threadIdx.x;
  s[i] = sp[i] + sp[MR_ + i] + sp[2 * MR_ + i] + sp[3 * MR_ + i];
}

__global__ __launch_bounds__(512) void softmax_kernel(float* __restrict__ s) {
  __shared__ float red[T_];
  const int b = blockIdx.x, t = threadIdx.x;
  const float v = s[b * T_ + t];
  red[t] = v;
  __syncthreads();
  for (int o = 256; o; o >>= 1) {
    if (t < o) red[t] = fmaxf(red[t], red[t + o]);
    __syncthreads();
  }
  const float m = red[0];
  __syncthreads();
  const float ev = expf(v - m);
  red[t] = ev;
  __syncthreads();
  for (int o = 256; o; o >>= 1) {
    if (t < o) red[t] += red[t + o];
    __syncthreads();
  }
  s[b * T_ + t] = ev / red[0];
}

__global__ __launch_bounds__(512) void pool_kernel(
    const __nv_bfloat16* __restrict__ seq, const float* __restrict__ a,
    float* __restrict__ pool) {
  const int b = blockIdx.x, d = threadIdx.x;
  const __nv_bfloat16* p = seq + (size_t)b * T_ * H_ + d;
  const float* ap = a + b * T_;
  float acc = 0.f;
  for (int t = 0; t < T_; t++)
    acc += ap[t] * __bfloat162float(p[(size_t)t * H_]);
  pool[b * H_ + d] = acc * (1.0f / T_);
}

__global__ __launch_bounds__(128) void head_kernel(
    const float* __restrict__ pool,
    const float* __restrict__ Wd1, const float* __restrict__ bd1,
    const float* __restrict__ bng, const float* __restrict__ bnb,
    const float* __restrict__ bnm, const float* __restrict__ bnv,
    const float* __restrict__ Wd2, const float* __restrict__ bd2,
    const float* __restrict__ Wd3, const float* __restrict__ bd3,
    float* __restrict__ out) {
  __shared__ float sp[H_];
  __shared__ float d1[128];
  __shared__ float d2[64];
  const int b = blockIdx.x, t = threadIdx.x;
  for (int i = t; i < H_; i += 128) sp[i] = pool[b * H_ + i];
  __syncthreads();
  {
    float acc = bd1[t];
    for (int k = 0; k < H_; k++) acc += sp[k] * Wd1[k * 128 + t];
    acc = fmaxf(acc, 0.f);
    acc = (acc - bnm[t]) * rsqrtf(bnv[t] + EPS_) * bng[t] + bnb[t];
    d1[t] = acc;
  }
  __syncthreads();
  if (t < 64) {
    float acc = bd2[t];
    for (int k = 0; k < 128; k++) acc += d1[k] * Wd2[k * 64 + t];
    d2[t] = fmaxf(acc, 0.f);
  }
  __syncthreads();
  if (t < 5) {
    float acc = bd3[t];
    for (int k = 0; k < 64; k++) acc += d2[k] * Wd3[k * 5 + t];
    out[b * 5 + t] = acc;
  }
}

// ---------------- launch ----------------------------------------------------
extern "C" void kernel_launch(void* const* d_in, const int* in_sizes, int n_in,
                              void* d_out, int out_size) {
  (void)out_size;
  static const int sig_map[30] = {0, 1, 2, 3, 8, 9, 10, 15, 16, 17,
                                  4, 5, 6, 7, 11, 12, 13, 14, 22, 23,
                                  24, 25, 18, 19, 20, 21, 26, 27, 28, 29};
  const int setup_order = (n_in >= 5 && in_sizes[4] == 1048576) ? 1 : 0;
  const float* in[30];
  for (int i = 0; i < 30; i++)
    in[i] = (const float*)d_in[setup_order ? i : sig_map[i]];

  const float* x = in[0];
  const float* Wl[3] = {in[1], in[4], in[7]};
  const float* Ul[3] = {in[2], in[5], in[8]};
  const float* bl[3] = {in[3], in[6], in[9]};
  const float* bng[3] = {in[10], in[14], in[18]};
  const float* bnb[3] = {in[11], in[15], in[19]};
  const float* bnm[3] = {in[12], in[16], in[20]};
  const float* bnv[3] = {in[13], in[17], in[21]};
  const float* Wa = in[22];  const float* ba = in[23];
  const float* Wd1 = in[24]; const float* bd1 = in[25];
  const float* Wd2 = in[26]; const float* bd2 = in[27];
  const float* Wd3 = in[28]; const float* bd3 = in[29];

  float *spart, *s, *pool;
  __nv_bfloat16 *xz, *seqA, *seqB, *hbuf;
  cudaGetSymbolAddress((void**)&xz, g_xz);
  cudaGetSymbolAddress((void**)&seqA, g_seqA);
  cudaGetSymbolAddress((void**)&seqB, g_seqB);
  cudaGetSymbolAddress((void**)&hbuf, g_hbuf);
  cudaGetSymbolAddress((void**)&spart, g_spart);
  cudaGetSymbolAddress((void**)&s, g_s);
  cudaGetSymbolAddress((void**)&pool, g_pool);

  cudaFuncSetAttribute(lstm_scan, cudaFuncAttributeMaxDynamicSharedMemorySize,
                       SMEM_SCAN);

  gemm_bf16k<false, false><<<dim3(G_ / 128, MR_ / 128), 256>>>(
      x, Wl[0], bl[0], xz, nullptr, D_, G_);
  lstm_scan<<<NBLK_, 256, SMEM_SCAN>>>(xz, Ul[0], seqA, hbuf,
                                       bng[0], bnb[0], bnm[0], bnv[0], 1);
  gemm_bf16k<true, false><<<dim3(G_ / 128, MR_ / 128), 256>>>(
      seqA, Wl[1], bl[1], xz, nullptr, H_, G_);
  lstm_scan<<<NBLK_, 256, SMEM_SCAN>>>(xz, Ul[1], seqB, hbuf,
                                       bng[1], bnb[1], bnm[1], bnv[1], 1);
  gemm_bf16k<true, false><<<dim3(G_ / 128, MR_ / 128), 256>>>(
      seqB, Wl[2], bl[2], xz, nullptr, H_, G_);
  lstm_scan<<<NBLK_, 256, SMEM_SCAN>>>(xz, Ul[2], seqA, hbuf,
                                       bng[2], bnb[2], bnm[2], bnv[2], 0);

  gemm_bf16k<true, true><<<dim3(H_ / 128, MR_ / 128), 256>>>(
      seqA, Wa, ba, nullptr, spart, H_, H_);
  rowsum_final<<<MR_ / 256, 256>>>(spart, s);
  softmax_kernel<<<B_, T_>>>(s);
  pool_kernel<<<B_, H_>>>(seqA, s, pool);
  head_kernel<<<B_, 128>>>(pool, Wd1, bd1, bng[2], bnb[2], bnm[2], bnv[2],
                           Wd2, bd2, Wd3, bd3, (float*)d_out);
}

// round 17
// speedup vs baseline: 3.0716x; 1.2328x over previous
#include <cuda_runtime.h>
#include <cuda_bf16.h>
#include <math.h>
#include <stdint.h>

#define B_ 128
#define T_ 512
#define D_ 128
#define H_ 512
#define G_ 2048          // 4*H
#define EPS_ 1e-3f
#define NBLK_ 128
#define MR_ (B_ * T_)    // 65536

// ---------------- scratch (static device allocations) -----------------------
__device__ __align__(16) __nv_bfloat16 g_xz[(size_t)B_ * T_ * G_];
__device__ __align__(16) __nv_bfloat16 g_seqA[(size_t)B_ * T_ * H_];
__device__ __align__(16) __nv_bfloat16 g_seqB[(size_t)B_ * T_ * H_];
__device__ __align__(16) __nv_bfloat16 g_hbuf[2 * B_ * H_];   // colblock-major
__device__ __align__(16) __nv_bfloat16 g_xbf[(size_t)MR_ * D_];
__device__ __align__(16) __nv_bfloat16 g_wt0[(size_t)G_ * D_];   // W0^T bf16
__device__ __align__(16) __nv_bfloat16 g_wt1[(size_t)G_ * H_];   // W1^T
__device__ __align__(16) __nv_bfloat16 g_wt2[(size_t)G_ * H_];   // W2^T
__device__ __align__(16) __nv_bfloat16 g_wta[(size_t)H_ * H_];   // Wa^T
__device__ __align__(16) float g_spart[4 * MR_];
__device__ __align__(16) float g_s[MR_];
__device__ __align__(16) float g_pool[B_ * H_];
__device__ volatile int g_bar_count;
__device__ volatile int g_bar_sense;
__device__ int g_flags[NBLK_ * 32];

// ---------------- helpers ----------------------------------------------------
__device__ __forceinline__ uint32_t packbf(float lo, float hi) {
  __nv_bfloat162 v = __floats2bfloat162_rn(lo, hi);
  return *(uint32_t*)&v;
}
__device__ __forceinline__ float2 unpackbf(uint32_t u) {
  __nv_bfloat162 v = *(__nv_bfloat162*)&u;
  return __bfloat1622float2(v);
}
__device__ __forceinline__ void mma_bf16(float* d, const uint32_t* a,
                                         const uint32_t* b) {
  asm("mma.sync.aligned.m16n8k16.row.col.f32.bf16.bf16.f32 "
      "{%0,%1,%2,%3}, {%4,%5,%6,%7}, {%8,%9}, {%0,%1,%2,%3};"
      : "+f"(d[0]), "+f"(d[1]), "+f"(d[2]), "+f"(d[3])
      : "r"(a[0]), "r"(a[1]), "r"(a[2]), "r"(a[3]), "r"(b[0]), "r"(b[1]));
}
__device__ __forceinline__ void ldsm4(uint32_t& r0, uint32_t& r1, uint32_t& r2,
                                      uint32_t& r3, uint32_t addr) {
  asm volatile(
      "ldmatrix.sync.aligned.m8n8.x4.shared.b16 {%0,%1,%2,%3}, [%4];"
      : "=r"(r0), "=r"(r1), "=r"(r2), "=r"(r3) : "r"(addr));
}
__device__ __forceinline__ float tanha(float x) {
  float y;
  asm("tanh.approx.f32 %0, %1;" : "=f"(y) : "f"(x));
  return y;
}
__device__ __forceinline__ float siga(float x) {
  return fmaf(tanha(0.5f * x), 0.5f, 0.5f);
}

__device__ __forceinline__ void grid_bar_atomic(int& ls) {
  __syncthreads();
  if (threadIdx.x == 0) {
    __threadfence();
    const int s = ls ^ 1;
    ls = s;
    if (atomicAdd((int*)&g_bar_count, 1) == NBLK_ - 1) {
      g_bar_count = 0;
      __threadfence();
      g_bar_sense = s;
    } else {
      while (g_bar_sense != s) { }
    }
    __threadfence();
  }
  __syncthreads();
}

__device__ __forceinline__ void bar_release(int phase) {
  __syncthreads();
  if (threadIdx.x == 0) {
    asm volatile("st.release.gpu.global.b32 [%0], %1;"
                 :: "l"(&g_flags[blockIdx.x * 32]), "r"(phase) : "memory");
  }
}

// ---------------- pre-conversion kernels -------------------------------------
__global__ __launch_bounds__(256) void conv_x(const float* __restrict__ x,
                                              __nv_bfloat16* __restrict__ xb) {
  const size_t i = ((size_t)blockIdx.x * 256 + threadIdx.x) * 4;
  const float4 v = *(const float4*)&x[i];
  uint2 o;
  o.x = packbf(v.x, v.y);
  o.y = packbf(v.z, v.w);
  *(uint2*)&xb[i] = o;
}

// Wt[n][k] = bf16(W[k][n])
__global__ __launch_bounds__(256) void transpose_w(
    const float* __restrict__ W, __nv_bfloat16* __restrict__ Wt, int K, int N) {
  __shared__ float tile[32][33];
  const int n0 = blockIdx.x * 32, k0 = blockIdx.y * 32;
  const int tx = threadIdx.x & 31, ty = threadIdx.x >> 5;  // 32x8
#pragma unroll
  for (int i = 0; i < 32; i += 8)
    tile[ty + i][tx] = W[(size_t)(k0 + ty + i) * N + n0 + tx];
  __syncthreads();
#pragma unroll
  for (int i = 0; i < 32; i += 8)
    Wt[(size_t)(n0 + ty + i) * K + k0 + tx] = __float2bfloat16(tile[tx][ty + i]);
}

// ---------------- cp.async bf16 GEMM: C = A[M,K] @ Wt[N,K]^T + bias ----------
// Both operands K-major bf16. 2-stage cp.async pipeline, 2 CTAs/SM.
// smem (dynamic): As0,As1,Bs0,Bs1 each [128][36] u32 (18432B) + srow 1KB.
#define GSTG 4608                 // uint32 per stage-matrix (128*36)
#define SMEM_G (4 * GSTG * 4 + 128 * 2 * 4)

template <bool ATTN>
__global__ __launch_bounds__(256, 2) void gemm_cp(
    const __nv_bfloat16* __restrict__ A, const __nv_bfloat16* __restrict__ Wt,
    const float* __restrict__ bias, __nv_bfloat16* __restrict__ C,
    float* __restrict__ spart, int K, int N) {
  extern __shared__ uint32_t sm[];
  float* srow = (float*)(sm + 4 * GSTG);
  const int tid = threadIdx.x;
  const int warp = tid >> 5, lane = tid & 31;
  const int wm = warp >> 1, wn = warp & 1;
  const int m0 = wm * 32, n0 = wn * 64;
  const int r = lane >> 2, c4 = lane & 3;
  const int row0 = blockIdx.y * 128, col0 = blockIdx.x * 128;
  const int quad = lane >> 3, l7 = lane & 7;
  const int lrow = l7 + ((quad & 1) << 3);
  const int lkof = (quad >> 1) << 2;

  float acc[2][8][4];
#pragma unroll
  for (int i = 0; i < 2; i++)
#pragma unroll
    for (int j = 0; j < 8; j++)
#pragma unroll
      for (int k = 0; k < 4; k++) acc[i][j][k] = 0.f;

  // ldsm bases (stage 0); stage 1 = +GSTG*4 bytes
  uint32_t aB[2], bB[4];
#pragma unroll
  for (int mf = 0; mf < 2; mf++)
    aB[mf] = (uint32_t)__cvta_generic_to_shared(
        &sm[(m0 + mf * 16 + lrow) * 36 + lkof]);
#pragma unroll
  for (int p = 0; p < 4; p++)
    bB[p] = (uint32_t)__cvta_generic_to_shared(
        &sm[2 * GSTG + (n0 + p * 16 + lrow) * 36 + lkof]);

  const int fr = tid >> 3, fc = (tid & 7);  // 32 rows/iter, 8 chunks per row

#define ISSUE_TILE(KT, STG) do {                                             \
    _Pragma("unroll")                                                        \
    for (int i_ = 0; i_ < 4; i_++) {                                         \
      const int row_ = fr + i_ * 32;                                         \
      uint32_t da_ = (uint32_t)__cvta_generic_to_shared(                     \
          &sm[(size_t)(STG)*GSTG + row_ * 36 + fc * 4]);                     \
      const void* sa_ = &A[(size_t)(row0 + row_) * K + (KT) + fc * 8];       \
      asm volatile("cp.async.cg.shared.global [%0], [%1], 16;" ::            \
                   "r"(da_), "l"(sa_));                                      \
      uint32_t db_ = (uint32_t)__cvta_generic_to_shared(                     \
          &sm[2 * GSTG + (size_t)(STG)*GSTG + row_ * 36 + fc * 4]);          \
      const void* sb_ = &Wt[(size_t)(col0 + row_) * K + (KT) + fc * 8];      \
      asm volatile("cp.async.cg.shared.global [%0], [%1], 16;" ::            \
                   "r"(db_), "l"(sb_));                                      \
    }                                                                        \
    asm volatile("cp.async.commit_group;");                                  \
  } while (0)

  ISSUE_TILE(0, 0);
  const int NIT = K >> 6;
  for (int it = 0; it < NIT; it++) {
    if (it + 1 < NIT) {
      ISSUE_TILE((it + 1) * 64, (it + 1) & 1);
      asm volatile("cp.async.wait_group 1;");
    } else {
      asm volatile("cp.async.wait_group 0;");
    }
    __syncthreads();
    const uint32_t soff = (uint32_t)(it & 1) * (GSTG * 4);
#pragma unroll
    for (int ck = 0; ck < 4; ck++) {
      const uint32_t koff = soff + ck * 32;
      uint32_t af[2][4], bf[8][2];
#pragma unroll
      for (int mf = 0; mf < 2; mf++)
        ldsm4(af[mf][0], af[mf][1], af[mf][2], af[mf][3], aB[mf] + koff);
#pragma unroll
      for (int p = 0; p < 4; p++)
        ldsm4(bf[2 * p][0], bf[2 * p + 1][0], bf[2 * p][1], bf[2 * p + 1][1],
              bB[p] + koff);
#pragma unroll
      for (int mf = 0; mf < 2; mf++)
#pragma unroll
        for (int nf = 0; nf < 8; nf++) mma_bf16(acc[mf][nf], af[mf], bf[nf]);
    }
    __syncthreads();  // stage reuse guard
  }
#undef ISSUE_TILE

  if (!ATTN) {
#pragma unroll
    for (int mf = 0; mf < 2; mf++) {
#pragma unroll
      for (int nf = 0; nf < 8; nf++) {
        const int cc = col0 + n0 + nf * 8 + c4 * 2;
        const float b0 = bias[cc], b1 = bias[cc + 1];
        const int rr = row0 + m0 + mf * 16 + r;
        *(uint32_t*)&C[(size_t)rr * N + cc] =
            packbf(acc[mf][nf][0] + b0, acc[mf][nf][1] + b1);
        *(uint32_t*)&C[(size_t)(rr + 8) * N + cc] =
            packbf(acc[mf][nf][2] + b0, acc[mf][nf][3] + b1);
      }
    }
  } else {
    float s0[2] = {0.f, 0.f}, s1[2] = {0.f, 0.f};
#pragma unroll
    for (int mf = 0; mf < 2; mf++) {
#pragma unroll
      for (int nf = 0; nf < 8; nf++) {
        const int cc = col0 + n0 + nf * 8 + c4 * 2;
        const float b0 = bias[cc], b1 = bias[cc + 1];
        s0[mf] += tanhf(acc[mf][nf][0] + b0) + tanhf(acc[mf][nf][1] + b1);
        s1[mf] += tanhf(acc[mf][nf][2] + b0) + tanhf(acc[mf][nf][3] + b1);
      }
#pragma unroll
      for (int o = 1; o < 4; o <<= 1) {
        s0[mf] += __shfl_xor_sync(0xFFFFFFFFu, s0[mf], o);
        s1[mf] += __shfl_xor_sync(0xFFFFFFFFu, s1[mf], o);
      }
    }
    if (c4 == 0) {
#pragma unroll
      for (int mf = 0; mf < 2; mf++) {
        srow[(m0 + mf * 16 + r) * 2 + wn] = s0[mf];
        srow[(m0 + mf * 16 + 8 + r) * 2 + wn] = s1[mf];
      }
    }
    __syncthreads();
    if (tid < 128)
      spart[(size_t)blockIdx.x * MR_ + row0 + tid] =
          srow[tid * 2] + srow[tid * 2 + 1];
  }
}

// ---------------- persistent LSTM scan (identical to 7788us best) -----------
#define SCPAD 260
#define ZPAD 33
#define SMEM_SCAN ((128 * SCPAD + 16 * SCPAD) * 4 + 4 * 16 * ZPAD * 4)

__global__ __launch_bounds__(256) void lstm_scan(
    const __nv_bfloat16* __restrict__ xz, const float* __restrict__ U,
    __nv_bfloat16* __restrict__ seqbf, __nv_bfloat16* __restrict__ hbuf,
    const float* __restrict__ bng, const float* __restrict__ bnb,
    const float* __restrict__ bnm, const float* __restrict__ bnv,
    int apply_bn) {
  extern __shared__ uint32_t dsm[];
  uint32_t(*Us)[SCPAD] = (uint32_t(*)[SCPAD])dsm;
  uint32_t(*Asm)[SCPAD] = (uint32_t(*)[SCPAD])(dsm + 128 * SCPAD);
  float* zbuf = (float*)(dsm + 144 * SCPAD);

  const int bid = blockIdx.x, tid = threadIdx.x;
  const int mb = bid >> 4, jb = bid & 15;
  const int j0 = jb * 32, b0g = mb * 16;
  const int gbase = mb * 16;
  const int warp = tid >> 5, lane = tid & 31;
  const int q = warp >> 1, half = warp & 1;
  const int r = lane >> 2, c4 = lane & 3;
  const int quad = lane >> 3, l7 = lane & 7;
  const int lrow = l7 + ((quad & 1) << 3);
  const int lkof = (quad >> 1) << 2;

#pragma unroll
  for (int i = 0; i < 32; i++) {
    const int g = tid + i * 256;
    const int n4 = g & 31, k2 = g >> 5;
    const int qq = n4 >> 3, cg = n4 & 7;
    const int gcol = qq * 512 + j0 + cg * 4;
    const float4 lo = *(const float4*)&U[(size_t)(2 * k2) * G_ + gcol];
    const float4 hi = *(const float4*)&U[(size_t)(2 * k2 + 1) * G_ + gcol];
    Us[n4 * 4 + 0][k2] = packbf(lo.x, hi.x);
    Us[n4 * 4 + 1][k2] = packbf(lo.y, hi.y);
    Us[n4 * 4 + 2][k2] = packbf(lo.z, hi.z);
    Us[n4 * 4 + 3][k2] = packbf(lo.w, hi.w);
  }

  const uint32_t aBase = (uint32_t)__cvta_generic_to_shared(&Asm[lrow][lkof]);
  const uint32_t bBase = (uint32_t)__cvta_generic_to_shared(
      &Us[q * 32 + half * 16 + lrow][lkof]);

  const int bl = tid >> 4, jj = (tid & 15) * 2;
  const int bg = b0g + bl, jgl = j0 + jj;
  float c1 = 0.f, c2 = 0.f;
  float scl1 = 1.f, sft1 = 0.f, scl2 = 1.f, sft2 = 0.f;
  if (apply_bn) {
    scl1 = rsqrtf(bnv[jgl] + EPS_) * bng[jgl];
    sft1 = bnb[jgl] - bnm[jgl] * scl1;
    scl2 = rsqrtf(bnv[jgl + 1] + EPS_) * bng[jgl + 1];
    sft2 = bnb[jgl + 1] - bnm[jgl + 1] * scl2;
  }
  __nv_bfloat16* hw_base = hbuf + (size_t)jb * B_ * 32 + bg * 32 + jj;

  const int peer = warp * 2 + (lane >> 4);
  const int pl = lane & 15;
  const int* peer_flag = &g_flags[(gbase + peer) * 32];

  const __nv_bfloat16* xzb1 =
      xz + ((size_t)(b0g + r) * T_) * G_ + q * 512 + j0 + half * 16;
  const __nv_bfloat16* xzb2 =
      xz + ((size_t)(b0g + 8 + r) * T_) * G_ + q * 512 + j0 + half * 16;
  uint32_t xp[4];
#pragma unroll
  for (int nf = 0; nf < 2; nf++) {
    const int cA = nf * 8 + c4 * 2;
    xp[nf * 2 + 0] = __ldg((const uint32_t*)(xzb1 + cA));
    xp[nf * 2 + 1] = __ldg((const uint32_t*)(xzb2 + cA));
  }

  int ls = 0;
  if (tid == 0) {
    ls = g_bar_sense;
    g_flags[bid * 32] = 0;
  }
  grid_bar_atomic(ls);

  for (int t = 0; t < T_; t++) {
    float accA[2][4], accB[2][4];
#pragma unroll
    for (int i = 0; i < 2; i++)
#pragma unroll
      for (int j = 0; j < 4; j++) { accA[i][j] = 0.f; accB[i][j] = 0.f; }

    if (t > 0) {
      const __nv_bfloat16* hsrc = hbuf + (size_t)(t & 1) * B_ * H_;
      {
        int v;
        do {
          asm volatile("ld.acquire.gpu.global.b32 %0, [%1];"
                       : "=r"(v) : "l"(peer_flag));
        } while (v < t);
      }
      const uint4* src =
          (const uint4*)&hsrc[(size_t)peer * B_ * 32 + (b0g + pl) * 32];
      const uint4 v0 = __ldcg(src + 0);
      const uint4 v1 = __ldcg(src + 1);
      const uint4 v2 = __ldcg(src + 2);
      const uint4 v3 = __ldcg(src + 3);
      uint32_t* dst = &Asm[pl][peer * 16];
      *(uint4*)(dst + 0) = v0;
      *(uint4*)(dst + 4) = v1;
      *(uint4*)(dst + 8) = v2;
      *(uint4*)(dst + 12) = v3;
      __syncthreads();

#pragma unroll 8
      for (int ck = 0; ck < 16; ck++) {
        const uint32_t koff = (uint32_t)ck * 32;
        uint32_t af[4], b00, b10, b01, b11;
        ldsm4(af[0], af[1], af[2], af[3], aBase + koff);
        ldsm4(b00, b10, b01, b11, bBase + koff);
        uint32_t bf0[2] = {b00, b01}, bf1[2] = {b10, b11};
        mma_bf16(accA[0], af, bf0);
        mma_bf16(accA[1], af, bf1);
      }
#pragma unroll 8
      for (int ck = 16; ck < 32; ck++) {
        const uint32_t koff = (uint32_t)ck * 32;
        uint32_t af[4], b00, b10, b01, b11;
        ldsm4(af[0], af[1], af[2], af[3], aBase + koff);
        ldsm4(b00, b10, b01, b11, bBase + koff);
        uint32_t bf0[2] = {b00, b01}, bf1[2] = {b10, b11};
        mma_bf16(accB[0], af, bf0);
        mma_bf16(accB[1], af, bf1);
      }
    }

#pragma unroll
    for (int nf = 0; nf < 2; nf++) {
      const int col = half * 16 + nf * 8 + c4 * 2;
      float* zb = zbuf + (size_t)q * 16 * ZPAD;
      const float2 x1 = unpackbf(xp[nf * 2 + 0]);
      const float2 x2 = unpackbf(xp[nf * 2 + 1]);
      zb[r * ZPAD + col] = accA[nf][0] + accB[nf][0] + x1.x;
      zb[r * ZPAD + col + 1] = accA[nf][1] + accB[nf][1] + x1.y;
      zb[(r + 8) * ZPAD + col] = accA[nf][2] + accB[nf][2] + x2.x;
      zb[(r + 8) * ZPAD + col + 1] = accA[nf][3] + accB[nf][3] + x2.y;
    }
    __syncthreads();

    const float zi1 = zbuf[(0 * 16 + bl) * ZPAD + jj];
    const float zi2 = zbuf[(0 * 16 + bl) * ZPAD + jj + 1];
    const float zf1 = zbuf[(1 * 16 + bl) * ZPAD + jj];
    const float zf2 = zbuf[(1 * 16 + bl) * ZPAD + jj + 1];
    const float zg1 = zbuf[(2 * 16 + bl) * ZPAD + jj];
    const float zg2 = zbuf[(2 * 16 + bl) * ZPAD + jj + 1];
    const float zo1 = zbuf[(3 * 16 + bl) * ZPAD + jj];
    const float zo2 = zbuf[(3 * 16 + bl) * ZPAD + jj + 1];

    if (t + 1 < T_) {
#pragma unroll
      for (int nf = 0; nf < 2; nf++) {
        const int cA = nf * 8 + c4 * 2;
        xp[nf * 2 + 0] =
            __ldg((const uint32_t*)(xzb1 + (size_t)(t + 1) * G_ + cA));
        xp[nf * 2 + 1] =
            __ldg((const uint32_t*)(xzb2 + (size_t)(t + 1) * G_ + cA));
      }
    }

    const float i1 = siga(zi1), f1 = siga(zf1), g1 = tanha(zg1), o1 = siga(zo1);
    c1 = f1 * c1 + i1 * g1;
    const float h1 = o1 * tanha(c1);
    const float i2 = siga(zi2), f2 = siga(zf2), g2 = tanha(zg2), o2 = siga(zo2);
    c2 = f2 * c2 + i2 * g2;
    const float h2 = o2 * tanha(c2);

    *(uint32_t*)(hw_base + (size_t)((t + 1) & 1) * B_ * H_) = packbf(h1, h2);
    bar_release(t + 1);

    const float s1v = apply_bn ? (h1 * scl1 + sft1) : h1;
    const float s2v = apply_bn ? (h2 * scl2 + sft2) : h2;
    *(uint32_t*)&seqbf[((size_t)bg * T_ + t) * H_ + jgl] = packbf(s1v, s2v);
  }
}

// ---------------- attention tail / head -------------------------------------
__global__ void rowsum_final(const float* __restrict__ sp,
                             float* __restrict__ s) {
  const int i = blockIdx.x * blockDim.x + threadIdx.x;
  s[i] = sp[i] + sp[MR_ + i] + sp[2 * MR_ + i] + sp[3 * MR_ + i];
}

__global__ __launch_bounds__(512) void softmax_kernel(float* __restrict__ s) {
  __shared__ float red[T_];
  const int b = blockIdx.x, t = threadIdx.x;
  const float v = s[b * T_ + t];
  red[t] = v;
  __syncthreads();
  for (int o = 256; o; o >>= 1) {
    if (t < o) red[t] = fmaxf(red[t], red[t + o]);
    __syncthreads();
  }
  const float m = red[0];
  __syncthreads();
  const float ev = expf(v - m);
  red[t] = ev;
  __syncthreads();
  for (int o = 256; o; o >>= 1) {
    if (t < o) red[t] += red[t + o];
    __syncthreads();
  }
  s[b * T_ + t] = ev / red[0];
}

__global__ __launch_bounds__(512) void pool_kernel(
    const __nv_bfloat16* __restrict__ seq, const float* __restrict__ a,
    float* __restrict__ pool) {
  const int b = blockIdx.x, d = threadIdx.x;
  const __nv_bfloat16* p = seq + (size_t)b * T_ * H_ + d;
  const float* ap = a + b * T_;
  float acc = 0.f;
  for (int t = 0; t < T_; t++)
    acc += ap[t] * __bfloat162float(p[(size_t)t * H_]);
  pool[b * H_ + d] = acc * (1.0f / T_);
}

__global__ __launch_bounds__(128) void head_kernel(
    const float* __restrict__ pool,
    const float* __restrict__ Wd1, const float* __restrict__ bd1,
    const float* __restrict__ bng, const float* __restrict__ bnb,
    const float* __restrict__ bnm, const float* __restrict__ bnv,
    const float* __restrict__ Wd2, const float* __restrict__ bd2,
    const float* __restrict__ Wd3, const float* __restrict__ bd3,
    float* __restrict__ out) {
  __shared__ float sp[H_];
  __shared__ float d1[128];
  __shared__ float d2[64];
  const int b = blockIdx.x, t = threadIdx.x;
  for (int i = t; i < H_; i += 128) sp[i] = pool[b * H_ + i];
  __syncthreads();
  {
    float acc = bd1[t];
    for (int k = 0; k < H_; k++) acc += sp[k] * Wd1[k * 128 + t];
    acc = fmaxf(acc, 0.f);
    acc = (acc - bnm[t]) * rsqrtf(bnv[t] + EPS_) * bng[t] + bnb[t];
    d1[t] = acc;
  }
  __syncthreads();
  if (t < 64) {
    float acc = bd2[t];
    for (int k = 0; k < 128; k++) acc += d1[k] * Wd2[k * 64 + t];
    d2[t] = fmaxf(acc, 0.f);
  }
  __syncthreads();
  if (t < 5) {
    float acc = bd3[t];
    for (int k = 0; k < 64; k++) acc += d2[k] * Wd3[k * 5 + t];
    out[b * 5 + t] = acc;
  }
}

// ---------------- launch ----------------------------------------------------
extern "C" void kernel_launch(void* const* d_in, const int* in_sizes, int n_in,
                              void* d_out, int out_size) {
  (void)out_size;
  static const int sig_map[30] = {0, 1, 2, 3, 8, 9, 10, 15, 16, 17,
                                  4, 5, 6, 7, 11, 12, 13, 14, 22, 23,
                                  24, 25, 18, 19, 20, 21, 26, 27, 28, 29};
  const int setup_order = (n_in >= 5 && in_sizes[4] == 1048576) ? 1 : 0;
  const float* in[30];
  for (int i = 0; i < 30; i++)
    in[i] = (const float*)d_in[setup_order ? i : sig_map[i]];

  const float* x = in[0];
  const float* Wl[3] = {in[1], in[4], in[7]};
  const float* Ul[3] = {in[2], in[5], in[8]};
  const float* bl[3] = {in[3], in[6], in[9]};
  const float* bng[3] = {in[10], in[14], in[18]};
  const float* bnb[3] = {in[11], in[15], in[19]};
  const float* bnm[3] = {in[12], in[16], in[20]};
  const float* bnv[3] = {in[13], in[17], in[21]};
  const float* Wa = in[22];  const float* ba = in[23];
  const float* Wd1 = in[24]; const float* bd1 = in[25];
  const float* Wd2 = in[26]; const float* bd2 = in[27];
  const float* Wd3 = in[28]; const float* bd3 = in[29];

  float *spart, *s, *pool;
  __nv_bfloat16 *xz, *seqA, *seqB, *hbuf, *xbf, *wt0, *wt1, *wt2, *wta;
  cudaGetSymbolAddress((void**)&xz, g_xz);
  cudaGetSymbolAddress((void**)&seqA, g_seqA);
  cudaGetSymbolAddress((void**)&seqB, g_seqB);
  cudaGetSymbolAddress((void**)&hbuf, g_hbuf);
  cudaGetSymbolAddress((void**)&xbf, g_xbf);
  cudaGetSymbolAddress((void**)&wt0, g_wt0);
  cudaGetSymbolAddress((void**)&wt1, g_wt1);
  cudaGetSymbolAddress((void**)&wt2, g_wt2);
  cudaGetSymbolAddress((void**)&wta, g_wta);
  cudaGetSymbolAddress((void**)&spart, g_spart);
  cudaGetSymbolAddress((void**)&s, g_s);
  cudaGetSymbolAddress((void**)&pool, g_pool);

  cudaFuncSetAttribute(lstm_scan, cudaFuncAttributeMaxDynamicSharedMemorySize,
                       SMEM_SCAN);
  cudaFuncSetAttribute(gemm_cp<false>,
                       cudaFuncAttributeMaxDynamicSharedMemorySize, SMEM_G);
  cudaFuncSetAttribute(gemm_cp<true>,
                       cudaFuncAttributeMaxDynamicSharedMemorySize, SMEM_G);

  // pre-conversions (bf16 rounding identical to previous in-GEMM packbf)
  conv_x<<<MR_ * D_ / 1024, 256>>>(x, xbf);
  transpose_w<<<dim3(G_ / 32, D_ / 32), 256>>>(Wl[0], wt0, D_, G_);
  transpose_w<<<dim3(G_ / 32, H_ / 32), 256>>>(Wl[1], wt1, H_, G_);
  transpose_w<<<dim3(G_ / 32, H_ / 32), 256>>>(Wl[2], wt2, H_, G_);
  transpose_w<<<dim3(H_ / 32, H_ / 32), 256>>>(Wa, wta, H_, H_);

  gemm_cp<false><<<dim3(G_ / 128, MR_ / 128), 256, SMEM_G>>>(
      xbf, wt0, bl[0], xz, nullptr, D_, G_);
  lstm_scan<<<NBLK_, 256, SMEM_SCAN>>>(xz, Ul[0], seqA, hbuf,
                                       bng[0], bnb[0], bnm[0], bnv[0], 1);
  gemm_cp<false><<<dim3(G_ / 128, MR_ / 128), 256, SMEM_G>>>(
      seqA, wt1, bl[1], xz, nullptr, H_, G_);
  lstm_scan<<<NBLK_, 256, SMEM_SCAN>>>(xz, Ul[1], seqB, hbuf,
                                       bng[1], bnb[1], bnm[1], bnv[1], 1);
  gemm_cp<false><<<dim3(G_ / 128, MR_ / 128), 256, SMEM_G>>>(
      seqB, wt2, bl[2], xz, nullptr, H_, G_);
  lstm_scan<<<NBLK_, 256, SMEM_SCAN>>>(xz, Ul[2], seqA, hbuf,
                                       bng[2], bnb[2], bnm[2], bnv[2], 0);

  gemm_cp<true><<<dim3(H_ / 128, MR_ / 128), 256, SMEM_G>>>(
      seqA, wta, ba, nullptr, spart, H_, H_);
  rowsum_final<<<MR_ / 256, 256>>>(spart, s);
  softmax_kernel<<<B_, T_>>>(s);
  pool_kernel<<<B_, H_>>>(seqA, s, pool);
  head_kernel<<<B_, 128>>>(pool, Wd1, bd1, bng[2], bnb[2], bnm[2], bnv[2],
                           Wd2, bd2, Wd3, bd3, (float*)d_out);
}